// round 1
// baseline (speedup 1.0000x reference)
#include <cuda_runtime.h>
#include <cuda_bf16.h>
#include <math.h>

// Problem dims
#define BS   128
#define SLEN 256
#define EDIM 512
#define HDIM 1024
#define VDIM 32000
#define ROWS (BS * SLEN)        // 32768
#define KEO  (2 * HDIM)         // 2048
#define KX   (EDIM + 2 * HDIM)  // 2560
#define KCAT (3 * HDIM + EDIM)  // 3584
#define NG   (4 * HDIM)         // 4096

// GEMM tile config
#define TBM 128
#define TBN 64
#define TBK 16
#define NTHREADS 256

// ---------------- scratch (device globals; no allocation allowed) ------------
__device__ float g_hproj[BS * HDIM];
__device__ float g_spart[16 * ROWS];     // 16 partial score planes (col-tiles of H)
__device__ float g_attn[BS * SLEN];
__device__ float g_x[BS * KX];           // [embedded | weighted]
__device__ float g_cat[BS * KCAT];       // [h_new | weighted | embedded]
__device__ float g_gates[BS * NG];

// ---------------- embedding gather ------------------------------------------
__global__ void embed_kernel(const int* __restrict__ tok,
                             const float* __restrict__ emb_w) {
    int b = blockIdx.x;
    int t = tok[b];
    for (int e = threadIdx.x; e < EDIM; e += blockDim.x) {
        float v = emb_w[(size_t)t * EDIM + e];
        g_x[(size_t)b * KX + e] = v;
        g_cat[(size_t)b * KCAT + 3 * HDIM + e] = v;
    }
}

// ---------------- generic GEMM: C[m,n] = sum_k A[m,k]*B[n,k] (+bias)(+=C) ----
// M is always 128 (one row tile). grid.x = N/64.
__global__ __launch_bounds__(NTHREADS)
void gemm_tn(const float* __restrict__ A, int lda,
             const float* __restrict__ B, int ldb,
             float* __restrict__ C, int ldc,
             int K, const float* __restrict__ bias, int accumulate) {
    __shared__ float As[TBK][TBM];
    __shared__ float Bs[TBK][TBN];
    const int tid = threadIdx.x;
    const int col0 = blockIdx.x * TBN;
    const int tm0 = (tid >> 4) * 8;
    const int tn0 = (tid & 15) * 4;
    float acc[8][4] = {};

    for (int k0 = 0; k0 < K; k0 += TBK) {
#pragma unroll
        for (int t = 0; t < 2; ++t) {
            int lin = (tid + t * NTHREADS) * 4;
            int r = lin >> 4, cc = lin & 15;
            float4 v = *(const float4*)(A + (size_t)r * lda + k0 + cc);
            As[cc + 0][r] = v.x; As[cc + 1][r] = v.y;
            As[cc + 2][r] = v.z; As[cc + 3][r] = v.w;
        }
        {
            int lin = tid * 4;
            int r = lin >> 4, cc = lin & 15;
            float4 v = *(const float4*)(B + (size_t)(col0 + r) * ldb + k0 + cc);
            Bs[cc + 0][r] = v.x; Bs[cc + 1][r] = v.y;
            Bs[cc + 2][r] = v.z; Bs[cc + 3][r] = v.w;
        }
        __syncthreads();
#pragma unroll
        for (int k = 0; k < TBK; ++k) {
            float4 a0 = *(const float4*)&As[k][tm0];
            float4 a1 = *(const float4*)&As[k][tm0 + 4];
            float4 b0 = *(const float4*)&Bs[k][tn0];
            float a[8] = {a0.x, a0.y, a0.z, a0.w, a1.x, a1.y, a1.z, a1.w};
            float b[4] = {b0.x, b0.y, b0.z, b0.w};
#pragma unroll
            for (int i = 0; i < 8; ++i)
#pragma unroll
                for (int j = 0; j < 4; ++j)
                    acc[i][j] = fmaf(a[i], b[j], acc[i][j]);
        }
        __syncthreads();
    }
#pragma unroll
    for (int i = 0; i < 8; ++i) {
        float* crow = C + (size_t)(tm0 + i) * ldc + col0 + tn0;
#pragma unroll
        for (int j = 0; j < 4; ++j) {
            float v = acc[i][j];
            if (bias) v += bias[col0 + tn0 + j];
            if (accumulate) v += crow[j];
            crow[j] = v;
        }
    }
}

// ---------------- fused attention-energy GEMM + score reduce -----------------
// rows r = b*SLEN+s over [0,32768); C[r,h] = sum_d eo[r,d]*attn_w[h, HDIM+d]
// epilogue: partial_score[r] += sum_{h in tile} v[h]*tanh(C+hproj[b,h]+attn_b[h])
// grid: (16 col tiles, 256 row tiles). Deterministic (no atomics).
__global__ __launch_bounds__(NTHREADS)
void attn_energy_kernel(const float* __restrict__ eo,
                        const float* __restrict__ attn_w,
                        const float* __restrict__ attn_b,
                        const float* __restrict__ v_w) {
    __shared__ float As[TBK][TBM];
    __shared__ float Bs[TBK][TBN];
    __shared__ float red[TBM][16];
    const int tid = threadIdx.x;
    const int row0 = blockIdx.y * TBM;
    const int col0 = blockIdx.x * TBN;
    const int tm0 = (tid >> 4) * 8;
    const int tn0 = (tid & 15) * 4;
    const float* Bp = attn_w + HDIM;     // attn_w[:, H:], ldb = 3*HDIM
    float acc[8][4] = {};

    for (int k0 = 0; k0 < KEO; k0 += TBK) {
#pragma unroll
        for (int t = 0; t < 2; ++t) {
            int lin = (tid + t * NTHREADS) * 4;
            int r = lin >> 4, cc = lin & 15;
            float4 v = *(const float4*)(eo + (size_t)(row0 + r) * KEO + k0 + cc);
            As[cc + 0][r] = v.x; As[cc + 1][r] = v.y;
            As[cc + 2][r] = v.z; As[cc + 3][r] = v.w;
        }
        {
            int lin = tid * 4;
            int r = lin >> 4, cc = lin & 15;
            float4 v = *(const float4*)(Bp + (size_t)(col0 + r) * (3 * HDIM) + k0 + cc);
            Bs[cc + 0][r] = v.x; Bs[cc + 1][r] = v.y;
            Bs[cc + 2][r] = v.z; Bs[cc + 3][r] = v.w;
        }
        __syncthreads();
#pragma unroll
        for (int k = 0; k < TBK; ++k) {
            float4 a0 = *(const float4*)&As[k][tm0];
            float4 a1 = *(const float4*)&As[k][tm0 + 4];
            float4 b0 = *(const float4*)&Bs[k][tn0];
            float a[8] = {a0.x, a0.y, a0.z, a0.w, a1.x, a1.y, a1.z, a1.w};
            float b[4] = {b0.x, b0.y, b0.z, b0.w};
#pragma unroll
            for (int i = 0; i < 8; ++i)
#pragma unroll
                for (int j = 0; j < 4; ++j)
                    acc[i][j] = fmaf(a[i], b[j], acc[i][j]);
        }
        __syncthreads();
    }

    // epilogue: tanh + dot with v, reduce over the 64 h-columns of this tile
    const int b_idx = row0 >> 8;  // 128-row tile always inside one batch row
    float hp[4], ab[4], vv[4];
#pragma unroll
    for (int j = 0; j < 4; ++j) {
        int h = col0 + tn0 + j;
        hp[j] = g_hproj[(size_t)b_idx * HDIM + h];
        ab[j] = attn_b[h];
        vv[j] = v_w[h];
    }
#pragma unroll
    for (int i = 0; i < 8; ++i) {
        float p = 0.f;
#pragma unroll
        for (int j = 0; j < 4; ++j)
            p += vv[j] * tanhf(acc[i][j] + hp[j] + ab[j]);
        red[tm0 + i][tid & 15] = p;
    }
    __syncthreads();
    if (tid < TBM) {
        float s = 0.f;
#pragma unroll
        for (int j = 0; j < 16; ++j) s += red[tid][j];
        g_spart[(size_t)blockIdx.x * ROWS + row0 + tid] = s;
    }
}

// ---------------- softmax over seq (sums the 16 partial planes) --------------
__global__ void softmax_kernel() {
    __shared__ float sred[SLEN];
    int b = blockIdx.x, s = threadIdx.x;
    float sc = 0.f;
#pragma unroll
    for (int p = 0; p < 16; ++p) sc += g_spart[(size_t)p * ROWS + b * SLEN + s];
    sred[s] = sc; __syncthreads();
    for (int o = SLEN / 2; o > 0; o >>= 1) {
        if (s < o) sred[s] = fmaxf(sred[s], sred[s + o]);
        __syncthreads();
    }
    float m = sred[0]; __syncthreads();
    float e = expf(sc - m);
    sred[s] = e; __syncthreads();
    for (int o = SLEN / 2; o > 0; o >>= 1) {
        if (s < o) sred[s] += sred[s + o];
        __syncthreads();
    }
    g_attn[b * SLEN + s] = e / sred[0];
}

// ---------------- weighted = a @ eo ------------------------------------------
__global__ void weighted_kernel(const float* __restrict__ eo) {
    __shared__ float a_sh[SLEN];
    int b = blockIdx.y;
    int d = blockIdx.x * 256 + threadIdx.x;
    if (threadIdx.x < SLEN) a_sh[threadIdx.x] = g_attn[b * SLEN + threadIdx.x];
    __syncthreads();
    const float* eob = eo + (size_t)b * SLEN * KEO + d;
    float acc = 0.f;
#pragma unroll 8
    for (int s = 0; s < SLEN; ++s) acc = fmaf(a_sh[s], eob[(size_t)s * KEO], acc);
    g_x[(size_t)b * KX + EDIM + d] = acc;
    g_cat[(size_t)b * KCAT + HDIM + d] = acc;
}

// ---------------- LSTM cell elementwise --------------------------------------
__global__ void lstm_kernel(const float* __restrict__ c0,
                            const float* __restrict__ b_ih,
                            const float* __restrict__ b_hh,
                            float* __restrict__ out) {
    int idx = blockIdx.x * blockDim.x + threadIdx.x;   // [0, 128*1024)
    int b = idx >> 10, h = idx & 1023;
    const float* gr = g_gates + (size_t)b * NG;
    float ig = gr[h]            + b_ih[h]            + b_hh[h];
    float fg = gr[HDIM + h]     + b_ih[HDIM + h]     + b_hh[HDIM + h];
    float gg = gr[2 * HDIM + h] + b_ih[2 * HDIM + h] + b_hh[2 * HDIM + h];
    float og = gr[3 * HDIM + h] + b_ih[3 * HDIM + h] + b_hh[3 * HDIM + h];
    float si = 1.f / (1.f + expf(-ig));
    float sf = 1.f / (1.f + expf(-fg));
    float so = 1.f / (1.f + expf(-og));
    float cn = sf * c0[idx] + si * tanhf(gg);
    float hn = so * tanhf(cn);
    g_cat[(size_t)b * KCAT + h] = hn;
    out[(size_t)BS * VDIM + idx] = hn;                  // h_new
    out[(size_t)BS * VDIM + BS * HDIM + idx] = cn;      // c_new
}

// ---------------- launch -----------------------------------------------------
extern "C" void kernel_launch(void* const* d_in, const int* in_sizes, int n_in,
                              void* d_out, int out_size) {
    const int*   inp_tok = (const int*)  d_in[0];
    const float* h0      = (const float*)d_in[1];
    const float* c0      = (const float*)d_in[2];
    const float* eo      = (const float*)d_in[3];
    const float* emb_w   = (const float*)d_in[4];
    const float* attn_w  = (const float*)d_in[5];
    const float* attn_b  = (const float*)d_in[6];
    const float* v_w     = (const float*)d_in[7];
    const float* w_ih    = (const float*)d_in[8];
    const float* w_hh    = (const float*)d_in[9];
    const float* b_ih    = (const float*)d_in[10];
    const float* b_hh    = (const float*)d_in[11];
    const float* fco_w   = (const float*)d_in[12];
    const float* fco_b   = (const float*)d_in[13];
    float* out = (float*)d_out;

    float *p_hproj, *p_x, *p_cat, *p_gates;
    cudaGetSymbolAddress((void**)&p_hproj, g_hproj);
    cudaGetSymbolAddress((void**)&p_x,     g_x);
    cudaGetSymbolAddress((void**)&p_cat,   g_cat);
    cudaGetSymbolAddress((void**)&p_gates, g_gates);

    // 1. embedding gather -> g_x[:, :E], g_cat[:, 3H:]
    embed_kernel<<<BS, 256>>>(inp_tok, emb_w);

    // 2. h_proj = h0 @ attn_w[:, :H]^T
    gemm_tn<<<dim3(HDIM / TBN, 1), NTHREADS>>>(h0, HDIM, attn_w, 3 * HDIM,
                                               p_hproj, HDIM, HDIM, nullptr, 0);

    // 3. fused e_proj GEMM + tanh + v-dot -> partial scores
    attn_energy_kernel<<<dim3(HDIM / TBN, ROWS / TBM), NTHREADS>>>(eo, attn_w,
                                                                   attn_b, v_w);

    // 4. softmax over seq
    softmax_kernel<<<BS, SLEN>>>();

    // 5. weighted context -> g_x[:, E:], g_cat[:, H:3H]
    weighted_kernel<<<dim3(KEO / 256, BS), 256>>>(eo);

    // 6. gates = x @ w_ih^T + h0 @ w_hh^T
    gemm_tn<<<dim3(NG / TBN, 1), NTHREADS>>>(p_x, KX, w_ih, KX,
                                             p_gates, NG, KX, nullptr, 0);
    gemm_tn<<<dim3(NG / TBN, 1), NTHREADS>>>(h0, HDIM, w_hh, HDIM,
                                             p_gates, NG, HDIM, nullptr, 1);

    // 7. LSTM elementwise -> h_new/c_new into d_out, h_new into g_cat[:, :H]
    lstm_kernel<<<(BS * HDIM) / 256, 256>>>(c0, b_ih, b_hh, out);

    // 8. prediction = cat @ fco_w^T + fco_b
    gemm_tn<<<dim3(VDIM / TBN, 1), NTHREADS>>>(p_cat, KCAT, fco_w, KCAT,
                                               out, VDIM, KCAT, fco_b, 0);
}

// round 3
// speedup vs baseline: 2.2068x; 2.2068x over previous
#include <cuda_runtime.h>
#include <cuda_bf16.h>
#include <cstdint>
#include <math.h>

// Problem dims
#define BS   128
#define SLEN 256
#define EDIM 512
#define HDIM 1024
#define VDIM 32000
#define ROWS (BS * SLEN)        // 32768
#define KEO  (2 * HDIM)         // 2048
#define KX   (EDIM + 2 * HDIM)  // 2560
#define KCAT (3 * HDIM + EDIM)  // 3584
#define NG   (4 * HDIM)         // 4096

// SIMT GEMM tile config (small GEMM: h_proj)
#define TBM 128
#define TBN 64
#define TBK 16
#define NTHREADS 256

// mma.sync tile config: CTA 256 thr, tile 128(M) x 256(N), k-step 32
#define PADROW 80                // bytes per 32-bf16 row (40 elems) - conflict-free ldmatrix
#define SM_ALO 10240             // A_lo offset inside stage
#define SM_BH  20480             // B_hi offset
#define SM_BLO 20480             // B_lo offset relative to B_hi
#define STAGE  61440             // 2*10240 + 2*20480
#define DSMEM  (2 * STAGE)      // 122880

// ---------------- scratch (device globals; no allocation allowed) ------------
__device__ float g_hproj[BS * HDIM];
__device__ float g_score[ROWS];
__device__ float g_attn[BS * SLEN];
__device__ float g_x[BS * KX];
__device__ float g_cat[BS * KCAT];
__device__ float g_gatesp[2][BS * NG];
__device__ __align__(16) __nv_bfloat16 g_eo_hi[(size_t)ROWS * KEO];
__device__ __align__(16) __nv_bfloat16 g_eo_lo[(size_t)ROWS * KEO];
__device__ __align__(16) __nv_bfloat16 g_w_hi[(size_t)HDIM * KEO];
__device__ __align__(16) __nv_bfloat16 g_w_lo[(size_t)HDIM * KEO];
__device__ __align__(16) __nv_bfloat16 g_fco_hi[(size_t)VDIM * KCAT];
__device__ __align__(16) __nv_bfloat16 g_fco_lo[(size_t)VDIM * KCAT];
__device__ __align__(16) __nv_bfloat16 g_cat_hi[(size_t)BS * KCAT];
__device__ __align__(16) __nv_bfloat16 g_cat_lo[(size_t)BS * KCAT];
__device__ __align__(16) __nv_bfloat16 g_xh_hi[(size_t)BS * KCAT];
__device__ __align__(16) __nv_bfloat16 g_xh_lo[(size_t)BS * KCAT];
__device__ __align__(16) __nv_bfloat16 g_wg_hi[(size_t)NG * KCAT];
__device__ __align__(16) __nv_bfloat16 g_wg_lo[(size_t)NG * KCAT];

// ---------------- PTX helpers ------------------------------------------------
__device__ __forceinline__ uint32_t smem_u32(const void* p) {
    uint32_t a;
    asm("{ .reg .u64 t; cvta.to.shared.u64 t, %1; cvt.u32.u64 %0, t; }"
        : "=r"(a) : "l"(p));
    return a;
}

__device__ __forceinline__ void cp16(uint32_t dst, const void* src) {
    asm volatile("cp.async.cg.shared.global [%0], [%1], 16;"
                 :: "r"(dst), "l"(src) : "memory");
}
#define CP_COMMIT() asm volatile("cp.async.commit_group;" ::: "memory")
#define CP_WAIT(n)  asm volatile("cp.async.wait_group %0;" :: "n"(n) : "memory")

__device__ __forceinline__ void ldmx4(uint32_t* r, uint32_t addr) {
    asm volatile("ldmatrix.sync.aligned.m8n8.x4.shared.b16 {%0,%1,%2,%3}, [%4];"
                 : "=r"(r[0]), "=r"(r[1]), "=r"(r[2]), "=r"(r[3]) : "r"(addr));
}

__device__ __forceinline__ void mma16816(float* d, const uint32_t* a,
                                         const uint32_t* b) {
    asm volatile(
        "mma.sync.aligned.m16n8k16.row.col.f32.bf16.bf16.f32 "
        "{%0,%1,%2,%3}, {%4,%5,%6,%7}, {%8,%9}, {%0,%1,%2,%3};"
        : "+f"(d[0]), "+f"(d[1]), "+f"(d[2]), "+f"(d[3])
        : "r"(a[0]), "r"(a[1]), "r"(a[2]), "r"(a[3]), "r"(b[0]), "r"(b[1]));
}

__device__ __forceinline__ float ftanh(float x) {
    float e = __expf(2.f * x);
    return 1.f - 2.f / (e + 1.f);
}

// ---------------- split-bf16 mma mainloop ------------------------------------
__device__ __forceinline__ void stage_load(
    uint32_t sbase,
    const __nv_bfloat16* __restrict__ Ah, const __nv_bfloat16* __restrict__ Al,
    int lda,
    const __nv_bfloat16* __restrict__ Bh, const __nv_bfloat16* __restrict__ Bl,
    int ldb, int tid, int kof)
{
#pragma unroll
    for (int i = 0; i < 2; ++i) {           // A: 128 rows x 32 k (hi & lo)
        int idx = tid + 256 * i;
        int r = idx >> 2, c = idx & 3;
        uint32_t d = sbase + r * PADROW + c * 16;
        size_t go = (size_t)r * lda + kof + c * 8;
        cp16(d, Ah + go);
        cp16(d + SM_ALO, Al + go);
    }
#pragma unroll
    for (int i = 0; i < 4; ++i) {           // B: 256 rows x 32 k (hi & lo)
        int idx = tid + 256 * i;
        int r = idx >> 2, c = idx & 3;
        uint32_t d = sbase + SM_BH + r * PADROW + c * 16;
        size_t go = (size_t)r * ldb + kof + c * 8;
        cp16(d, Bh + go);
        cp16(d + SM_BLO, Bl + go);
    }
}

__device__ __forceinline__ void stage_compute(uint32_t sbase, int lane,
                                              int wm, int wn,
                                              float (&acc)[4][8][4])
{
    const uint32_t a_row = wm * 64 + (lane & 7) + ((lane >> 3) & 1) * 8;
    const uint32_t a_colb = (lane >> 4) * 16;
    const uint32_t b_row = wn * 64 + (lane & 7) + ((lane >> 4) & 1) * 8;
    const uint32_t b_colb = ((lane >> 3) & 1) * 16;
#pragma unroll
    for (int kk = 0; kk < 2; ++kk) {
        uint32_t ahi[4][4], alo[4][4], bfr[4][4];
        const uint32_t ka = sbase + a_row * PADROW + a_colb + kk * 32;
#pragma unroll
        for (int mt = 0; mt < 4; ++mt) {
            ldmx4(ahi[mt], ka + mt * 16 * PADROW);
            ldmx4(alo[mt], ka + mt * 16 * PADROW + SM_ALO);
        }
        const uint32_t kb = sbase + SM_BH + b_row * PADROW + b_colb + kk * 32;
#pragma unroll
        for (int np = 0; np < 4; ++np) ldmx4(bfr[np], kb + np * 16 * PADROW);
#pragma unroll
        for (int mt = 0; mt < 4; ++mt)
#pragma unroll
            for (int np = 0; np < 4; ++np) {
                mma16816(acc[mt][np * 2],     ahi[mt], &bfr[np][0]);
                mma16816(acc[mt][np * 2 + 1], ahi[mt], &bfr[np][2]);
                mma16816(acc[mt][np * 2],     alo[mt], &bfr[np][0]);
                mma16816(acc[mt][np * 2 + 1], alo[mt], &bfr[np][2]);
            }
#pragma unroll
        for (int np = 0; np < 4; ++np)
            ldmx4(bfr[np], kb + np * 16 * PADROW + SM_BLO);
#pragma unroll
        for (int mt = 0; mt < 4; ++mt)
#pragma unroll
            for (int np = 0; np < 4; ++np) {
                mma16816(acc[mt][np * 2],     ahi[mt], &bfr[np][0]);
                mma16816(acc[mt][np * 2 + 1], ahi[mt], &bfr[np][2]);
            }
    }
}

__device__ __forceinline__ void gemm_mainloop(
    const __nv_bfloat16* Ah, const __nv_bfloat16* Al, int lda,
    const __nv_bfloat16* Bh, const __nv_bfloat16* Bl, int ldb,
    int KT, uint32_t sm0, int tid, float (&acc)[4][8][4])
{
    const int lane = tid & 31, wid = tid >> 5;
    const int wm = wid >> 2, wn = wid & 3;
    stage_load(sm0, Ah, Al, lda, Bh, Bl, ldb, tid, 0);
    CP_COMMIT();
    for (int it = 0; it < KT; ++it) {
        if (it + 1 < KT) {
            stage_load(sm0 + ((it + 1) & 1) * STAGE, Ah, Al, lda, Bh, Bl, ldb,
                       tid, (it + 1) * 32);
            CP_COMMIT();
            CP_WAIT(1);
        } else {
            CP_WAIT(0);
        }
        __syncthreads();
        stage_compute(sm0 + (it & 1) * STAGE, lane, wm, wn, acc);
        __syncthreads();
    }
}

// ---------------- fp32 -> bf16 hi/lo split conversions -----------------------
__device__ __forceinline__ void split1(float a, __nv_bfloat16& h, __nv_bfloat16& l) {
    h = __float2bfloat16(a);
    l = __float2bfloat16(a - __bfloat162float(h));
}

__global__ void conv_split(const float4* __restrict__ src,
                           __nv_bfloat162* __restrict__ hi,
                           __nv_bfloat162* __restrict__ lo) {
    size_t i = (size_t)blockIdx.x * blockDim.x + threadIdx.x;
    float4 v = src[i];
    __nv_bfloat16 h0, h1, h2, h3, l0, l1, l2, l3;
    split1(v.x, h0, l0); split1(v.y, h1, l1);
    split1(v.z, h2, l2); split1(v.w, h3, l3);
    hi[i * 2 + 0] = __halves2bfloat162(h0, h1);
    hi[i * 2 + 1] = __halves2bfloat162(h2, h3);
    lo[i * 2 + 0] = __halves2bfloat162(l0, l1);
    lo[i * 2 + 1] = __halves2bfloat162(l2, l3);
}

// gather attn_w[:, H:3H] -> g_w_hi/lo [HDIM x KEO]
__global__ void conv_w_kernel(const float* __restrict__ attn_w) {
    int n = blockIdx.x;
    const float* src = attn_w + (size_t)n * 3 * HDIM + HDIM;
    for (int c = threadIdx.x; c < KEO; c += blockDim.x) {
        __nv_bfloat16 h, l;
        split1(src[c], h, l);
        g_w_hi[(size_t)n * KEO + c] = h;
        g_w_lo[(size_t)n * KEO + c] = l;
    }
}

// [w_ih | w_hh] rows -> g_wg [NG x KCAT]
__global__ void conv_wg_kernel(const float* __restrict__ w_ih,
                               const float* __restrict__ w_hh) {
    int n = blockIdx.x;
    for (int k = threadIdx.x; k < KCAT; k += blockDim.x) {
        float v = (k < KX) ? w_ih[(size_t)n * KX + k]
                           : w_hh[(size_t)n * HDIM + (k - KX)];
        __nv_bfloat16 h, l;
        split1(v, h, l);
        g_wg_hi[(size_t)n * KCAT + k] = h;
        g_wg_lo[(size_t)n * KCAT + k] = l;
    }
}

// [x | h0] rows -> g_xh [BS x KCAT]
__global__ void conv_xh_kernel(const float* __restrict__ h0) {
    int b = blockIdx.x;
    for (int k = threadIdx.x; k < KCAT; k += blockDim.x) {
        float v = (k < KX) ? g_x[(size_t)b * KX + k]
                           : h0[(size_t)b * HDIM + (k - KX)];
        __nv_bfloat16 h, l;
        split1(v, h, l);
        g_xh_hi[(size_t)b * KCAT + k] = h;
        g_xh_lo[(size_t)b * KCAT + k] = l;
    }
}

// ---------------- embedding gather ------------------------------------------
__global__ void embed_kernel(const int* __restrict__ tok,
                             const float* __restrict__ emb_w) {
    int b = blockIdx.x;
    int t = tok[b];
    for (int e = threadIdx.x; e < EDIM; e += blockDim.x) {
        float v = emb_w[(size_t)t * EDIM + e];
        g_x[(size_t)b * KX + e] = v;
        g_cat[(size_t)b * KCAT + 3 * HDIM + e] = v;
    }
}

// ---------------- SIMT GEMM (h_proj only) ------------------------------------
__global__ __launch_bounds__(NTHREADS)
void gemm_tn(const float* __restrict__ A, int lda,
             const float* __restrict__ B, int ldb,
             float* __restrict__ C, int ldc, int K) {
    __shared__ float As[TBK][TBM];
    __shared__ float Bs[TBK][TBN];
    const int tid = threadIdx.x;
    const int col0 = blockIdx.x * TBN;
    const int tm0 = (tid >> 4) * 8;
    const int tn0 = (tid & 15) * 4;
    float acc[8][4] = {};
    for (int k0 = 0; k0 < K; k0 += TBK) {
#pragma unroll
        for (int t = 0; t < 2; ++t) {
            int lin = (tid + t * NTHREADS) * 4;
            int r = lin >> 4, cc = lin & 15;
            float4 v = *(const float4*)(A + (size_t)r * lda + k0 + cc);
            As[cc + 0][r] = v.x; As[cc + 1][r] = v.y;
            As[cc + 2][r] = v.z; As[cc + 3][r] = v.w;
        }
        {
            int lin = tid * 4;
            int r = lin >> 4, cc = lin & 15;
            float4 v = *(const float4*)(B + (size_t)(col0 + r) * ldb + k0 + cc);
            Bs[cc + 0][r] = v.x; Bs[cc + 1][r] = v.y;
            Bs[cc + 2][r] = v.z; Bs[cc + 3][r] = v.w;
        }
        __syncthreads();
#pragma unroll
        for (int k = 0; k < TBK; ++k) {
            float4 a0 = *(const float4*)&As[k][tm0];
            float4 a1 = *(const float4*)&As[k][tm0 + 4];
            float4 b0 = *(const float4*)&Bs[k][tn0];
            float a[8] = {a0.x, a0.y, a0.z, a0.w, a1.x, a1.y, a1.z, a1.w};
            float b[4] = {b0.x, b0.y, b0.z, b0.w};
#pragma unroll
            for (int i = 0; i < 8; ++i)
#pragma unroll
                for (int j = 0; j < 4; ++j)
                    acc[i][j] = fmaf(a[i], b[j], acc[i][j]);
        }
        __syncthreads();
    }
#pragma unroll
    for (int i = 0; i < 8; ++i)
#pragma unroll
        for (int j = 0; j < 4; ++j)
            C[(size_t)(tm0 + i) * ldc + col0 + tn0 + j] = acc[i][j];
}

// ================= attention energy: mma + fused tanh/v epilogue =============
// grid 128; each CTA: 2 M-tiles of 128 rows, 4 N-chunks of 256 over K=2048.
__global__ __launch_bounds__(256, 1)
void attn_mma(const float* __restrict__ attn_b, const float* __restrict__ v_w) {
    extern __shared__ char dsm[];
    __shared__ float base_sh[256], v_sh[256], red[4][128];
    const uint32_t sm0 = smem_u32(dsm);
    const int tid = threadIdx.x, lane = tid & 31, wid = tid >> 5;
    const int wm = wid >> 2, wn = wid & 3;

    for (int mp = 0; mp < 2; ++mp) {
        const int row0 = (blockIdx.x + mp * 128) * 128;
        const int b_idx = row0 >> 8;
        float rowpart[4][2] = {};
        for (int ch = 0; ch < 4; ++ch) {
            const int n0 = ch * 256;
            __syncthreads();
            base_sh[tid] = g_hproj[(size_t)b_idx * HDIM + n0 + tid] + attn_b[n0 + tid];
            v_sh[tid] = v_w[n0 + tid];
            float acc[4][8][4] = {};
            gemm_mainloop(g_eo_hi + (size_t)row0 * KEO,
                          g_eo_lo + (size_t)row0 * KEO, KEO,
                          g_w_hi + (size_t)n0 * KEO,
                          g_w_lo + (size_t)n0 * KEO, KEO,
                          64, sm0, tid, acc);
#pragma unroll
            for (int mt = 0; mt < 4; ++mt)
#pragma unroll
                for (int nt = 0; nt < 8; ++nt) {
                    int nb = wn * 64 + nt * 8 + (lane & 3) * 2;
                    float b0 = base_sh[nb], b1 = base_sh[nb + 1];
                    float v0 = v_sh[nb], v1 = v_sh[nb + 1];
                    rowpart[mt][0] += v0 * ftanh(acc[mt][nt][0] + b0)
                                    + v1 * ftanh(acc[mt][nt][1] + b1);
                    rowpart[mt][1] += v0 * ftanh(acc[mt][nt][2] + b0)
                                    + v1 * ftanh(acc[mt][nt][3] + b1);
                }
        }
        // reduce over 4 lanes sharing row, then over 4 warp_n
#pragma unroll
        for (int mt = 0; mt < 4; ++mt)
#pragma unroll
            for (int h = 0; h < 2; ++h) {
                float v = rowpart[mt][h];
                v += __shfl_xor_sync(0xffffffff, v, 1);
                v += __shfl_xor_sync(0xffffffff, v, 2);
                if ((lane & 3) == 0)
                    red[wn][wm * 64 + mt * 16 + (lane >> 2) + 8 * h] = v;
            }
        __syncthreads();
        if (tid < 128)
            g_score[row0 + tid] = red[0][tid] + red[1][tid] + red[2][tid] + red[3][tid];
        __syncthreads();
    }
}

// ================= fc: prediction = cat @ fco^T + b ==========================
__global__ __launch_bounds__(256, 1)
void fc_mma(const float* __restrict__ fco_b, float* __restrict__ out) {
    extern __shared__ char dsm[];
    const uint32_t sm0 = smem_u32(dsm);
    const int tid = threadIdx.x, lane = tid & 31, wid = tid >> 5;
    const int wm = wid >> 2, wn = wid & 3;
    const int n0 = blockIdx.x * 256;
    float acc[4][8][4] = {};
    gemm_mainloop(g_cat_hi, g_cat_lo, KCAT,
                  g_fco_hi + (size_t)n0 * KCAT,
                  g_fco_lo + (size_t)n0 * KCAT, KCAT,
                  KCAT / 32, sm0, tid, acc);
#pragma unroll
    for (int mt = 0; mt < 4; ++mt) {
        int r0 = wm * 64 + mt * 16 + (lane >> 2);
#pragma unroll
        for (int nt = 0; nt < 8; ++nt) {
            int n = n0 + wn * 64 + nt * 8 + (lane & 3) * 2;
            float b0 = fco_b[n], b1 = fco_b[n + 1];
            out[(size_t)r0 * VDIM + n] = acc[mt][nt][0] + b0;
            out[(size_t)r0 * VDIM + n + 1] = acc[mt][nt][1] + b1;
            out[(size_t)(r0 + 8) * VDIM + n] = acc[mt][nt][2] + b0;
            out[(size_t)(r0 + 8) * VDIM + n + 1] = acc[mt][nt][3] + b1;
        }
    }
}

// ================= gates: [x|h] @ [w_ih|w_hh]^T, split-K=2 ===================
__global__ __launch_bounds__(256, 1)
void gates_mma() {
    extern __shared__ char dsm[];
    const uint32_t sm0 = smem_u32(dsm);
    const int tid = threadIdx.x, lane = tid & 31, wid = tid >> 5;
    const int wm = wid >> 2, wn = wid & 3;
    const int n0 = (blockIdx.x & 15) * 256;
    const int ks = blockIdx.x >> 4;
    const int kof = ks * (KCAT / 2);
    float acc[4][8][4] = {};
    gemm_mainloop(g_xh_hi + kof, g_xh_lo + kof, KCAT,
                  g_wg_hi + (size_t)n0 * KCAT + kof,
                  g_wg_lo + (size_t)n0 * KCAT + kof, KCAT,
                  KCAT / 64, sm0, tid, acc);
    float* gp = g_gatesp[ks];
#pragma unroll
    for (int mt = 0; mt < 4; ++mt) {
        int r0 = wm * 64 + mt * 16 + (lane >> 2);
#pragma unroll
        for (int nt = 0; nt < 8; ++nt) {
            int n = n0 + wn * 64 + nt * 8 + (lane & 3) * 2;
            gp[(size_t)r0 * NG + n] = acc[mt][nt][0];
            gp[(size_t)r0 * NG + n + 1] = acc[mt][nt][1];
            gp[(size_t)(r0 + 8) * NG + n] = acc[mt][nt][2];
            gp[(size_t)(r0 + 8) * NG + n + 1] = acc[mt][nt][3];
        }
    }
}

// ---------------- softmax over seq -------------------------------------------
__global__ void softmax_kernel() {
    __shared__ float sred[SLEN];
    int b = blockIdx.x, s = threadIdx.x;
    float sc = g_score[b * SLEN + s];
    sred[s] = sc; __syncthreads();
    for (int o = SLEN / 2; o > 0; o >>= 1) {
        if (s < o) sred[s] = fmaxf(sred[s], sred[s + o]);
        __syncthreads();
    }
    float m = sred[0]; __syncthreads();
    float e = expf(sc - m);
    sred[s] = e; __syncthreads();
    for (int o = SLEN / 2; o > 0; o >>= 1) {
        if (s < o) sred[s] += sred[s + o];
        __syncthreads();
    }
    g_attn[b * SLEN + s] = e / sred[0];
}

// ---------------- weighted = a @ eo ------------------------------------------
__global__ void weighted_kernel(const float* __restrict__ eo) {
    __shared__ float a_sh[SLEN];
    int b = blockIdx.y;
    int d = blockIdx.x * 256 + threadIdx.x;
    if (threadIdx.x < SLEN) a_sh[threadIdx.x] = g_attn[b * SLEN + threadIdx.x];
    __syncthreads();
    const float* eob = eo + (size_t)b * SLEN * KEO + d;
    float acc = 0.f;
#pragma unroll 8
    for (int s = 0; s < SLEN; ++s) acc = fmaf(a_sh[s], eob[(size_t)s * KEO], acc);
    g_x[(size_t)b * KX + EDIM + d] = acc;
    g_cat[(size_t)b * KCAT + HDIM + d] = acc;
}

// ---------------- LSTM cell elementwise --------------------------------------
__global__ void lstm_kernel(const float* __restrict__ c0,
                            const float* __restrict__ b_ih,
                            const float* __restrict__ b_hh,
                            float* __restrict__ out) {
    int idx = blockIdx.x * blockDim.x + threadIdx.x;   // [0, 128*1024)
    int b = idx >> 10, h = idx & 1023;
    const float* g0 = g_gatesp[0] + (size_t)b * NG;
    const float* g1 = g_gatesp[1] + (size_t)b * NG;
    float ig = g0[h]            + g1[h]            + b_ih[h]            + b_hh[h];
    float fg = g0[HDIM + h]     + g1[HDIM + h]     + b_ih[HDIM + h]     + b_hh[HDIM + h];
    float gg = g0[2 * HDIM + h] + g1[2 * HDIM + h] + b_ih[2 * HDIM + h] + b_hh[2 * HDIM + h];
    float og = g0[3 * HDIM + h] + g1[3 * HDIM + h] + b_ih[3 * HDIM + h] + b_hh[3 * HDIM + h];
    float si = 1.f / (1.f + expf(-ig));
    float sf = 1.f / (1.f + expf(-fg));
    float so = 1.f / (1.f + expf(-og));
    float cn = sf * c0[idx] + si * tanhf(gg);
    float hn = so * tanhf(cn);
    g_cat[(size_t)b * KCAT + h] = hn;
    out[(size_t)BS * VDIM + idx] = hn;                  // h_new
    out[(size_t)BS * VDIM + BS * HDIM + idx] = cn;      // c_new
}

// ---------------- launch -----------------------------------------------------
extern "C" void kernel_launch(void* const* d_in, const int* in_sizes, int n_in,
                              void* d_out, int out_size) {
    const int*   inp_tok = (const int*)  d_in[0];
    const float* h0      = (const float*)d_in[1];
    const float* c0      = (const float*)d_in[2];
    const float* eo      = (const float*)d_in[3];
    const float* emb_w   = (const float*)d_in[4];
    const float* attn_w  = (const float*)d_in[5];
    const float* attn_b  = (const float*)d_in[6];
    const float* v_w     = (const float*)d_in[7];
    const float* w_ih    = (const float*)d_in[8];
    const float* w_hh    = (const float*)d_in[9];
    const float* b_ih    = (const float*)d_in[10];
    const float* b_hh    = (const float*)d_in[11];
    const float* fco_w   = (const float*)d_in[12];
    const float* fco_b   = (const float*)d_in[13];
    float* out = (float*)d_out;

    float* p_hproj;
    cudaGetSymbolAddress((void**)&p_hproj, g_hproj);
    void *p_eo_hi, *p_eo_lo, *p_fco_hi, *p_fco_lo, *p_cat, *p_cat_hi, *p_cat_lo;
    cudaGetSymbolAddress(&p_eo_hi,  g_eo_hi);
    cudaGetSymbolAddress(&p_eo_lo,  g_eo_lo);
    cudaGetSymbolAddress(&p_fco_hi, g_fco_hi);
    cudaGetSymbolAddress(&p_fco_lo, g_fco_lo);
    cudaGetSymbolAddress(&p_cat,    g_cat);
    cudaGetSymbolAddress(&p_cat_hi, g_cat_hi);
    cudaGetSymbolAddress(&p_cat_lo, g_cat_lo);

    cudaFuncSetAttribute(attn_mma,  cudaFuncAttributeMaxDynamicSharedMemorySize, DSMEM);
    cudaFuncSetAttribute(fc_mma,    cudaFuncAttributeMaxDynamicSharedMemorySize, DSMEM);
    cudaFuncSetAttribute(gates_mma, cudaFuncAttributeMaxDynamicSharedMemorySize, DSMEM);

    // conversions (inputs may change per replay; must rerun)
    conv_split<<<(ROWS * (size_t)KEO) / 4 / 256, 256>>>(
        (const float4*)eo, (__nv_bfloat162*)p_eo_hi, (__nv_bfloat162*)p_eo_lo);
    conv_w_kernel<<<HDIM, 256>>>(attn_w);
    conv_split<<<((size_t)VDIM * KCAT) / 4 / 256, 256>>>(
        (const float4*)fco_w, (__nv_bfloat162*)p_fco_hi, (__nv_bfloat162*)p_fco_lo);
    conv_wg_kernel<<<NG, 256>>>(w_ih, w_hh);

    // embedding + h_proj
    embed_kernel<<<BS, 256>>>(inp_tok, emb_w);
    gemm_tn<<<HDIM / TBN, NTHREADS>>>(h0, HDIM, attn_w, 3 * HDIM,
                                      p_hproj, HDIM, HDIM);

    // attention scores (fused GEMM + tanh + v-dot)
    attn_mma<<<128, 256, DSMEM>>>(attn_b, v_w);
    softmax_kernel<<<BS, SLEN>>>();
    weighted_kernel<<<dim3(KEO / 256, BS), 256>>>(eo);

    // LSTM gates
    conv_xh_kernel<<<BS, 256>>>(h0);
    gates_mma<<<32, 256, DSMEM>>>();
    lstm_kernel<<<(BS * HDIM) / 256, 256>>>(c0, b_ih, b_hh, out);

    // output projection
    conv_split<<<((size_t)BS * KCAT) / 4 / 256, 256>>>(
        (const float4*)p_cat, (__nv_bfloat162*)p_cat_hi, (__nv_bfloat162*)p_cat_lo);
    fc_mma<<<VDIM / 256, 256, DSMEM>>>(fco_b, out);
}

// round 5
// speedup vs baseline: 2.8271x; 1.2811x over previous
#include <cuda_runtime.h>
#include <cuda_fp16.h>
#include <cstdint>
#include <math.h>

// Problem dims
#define BS   128
#define SLEN 256
#define EDIM 512
#define HDIM 1024
#define VDIM 32000
#define ROWS (BS * SLEN)        // 32768
#define KEO  (2 * HDIM)         // 2048
#define KX   (EDIM + 2 * HDIM)  // 2560
#define KCAT (3 * HDIM + EDIM)  // 3584
#define NG   (4 * HDIM)         // 4096

// SIMT GEMM tile config (h_proj only)
#define TBM 128
#define TBN 64
#define TBK 16
#define NTHREADS 256

// mma.sync tile: CTA 256 thr, tile 128(M) x 256(N), k-step 32, 3-stage pipeline
#define PADROW 80               // bytes per 32-half row - conflict-free ldmatrix
#define SM_ALO 10240            // A_lo offset inside stage
#define SM_BH  20480            // B_hi offset
#define SM_BLO 20480            // B_lo offset relative to B_hi
#define STAGE2 40960            // 2-term stage bytes
#define STAGE3 61440            // 3-term stage bytes
#define DSMEM2 (3 * STAGE2)     // 122880
#define DSMEM3 (3 * STAGE3)     // 184320

// ---------------- scratch (device globals; no allocation allowed) ------------
__device__ float g_hproj[BS * HDIM];
__device__ float g_score[ROWS];
__device__ float g_attn[BS * SLEN];
__device__ float g_x[BS * KX];
__device__ float g_cat[BS * KCAT];
__device__ float g_gatesp[2][BS * NG];
__device__ __align__(16) __half g_eo_hi[(size_t)ROWS * KEO];
__device__ __align__(16) __half g_eo_lo[(size_t)ROWS * KEO];
__device__ __align__(16) __half g_w_hi[(size_t)HDIM * KEO];
__device__ __align__(16) __half g_fco_hi[(size_t)VDIM * KCAT];
__device__ __align__(16) __half g_fco_lo[(size_t)VDIM * KCAT];
__device__ __align__(16) __half g_cat_hi[(size_t)BS * KCAT];
__device__ __align__(16) __half g_cat_lo[(size_t)BS * KCAT];
__device__ __align__(16) __half g_xh_hi[(size_t)BS * KCAT];
__device__ __align__(16) __half g_xh_lo[(size_t)BS * KCAT];
__device__ __align__(16) __half g_wg_hi[(size_t)NG * KCAT];

// ---------------- PTX helpers ------------------------------------------------
__device__ __forceinline__ uint32_t smem_u32(const void* p) {
    uint32_t a;
    asm("{ .reg .u64 t; cvta.to.shared.u64 t, %1; cvt.u32.u64 %0, t; }"
        : "=r"(a) : "l"(p));
    return a;
}

__device__ __forceinline__ void cp16(uint32_t dst, const void* src) {
    asm volatile("cp.async.cg.shared.global [%0], [%1], 16;"
                 :: "r"(dst), "l"(src) : "memory");
}
#define CP_COMMIT() asm volatile("cp.async.commit_group;" ::: "memory")
#define CP_WAIT(n)  asm volatile("cp.async.wait_group %0;" :: "n"(n) : "memory")

__device__ __forceinline__ void ldmx4(uint32_t* r, uint32_t addr) {
    asm volatile("ldmatrix.sync.aligned.m8n8.x4.shared.b16 {%0,%1,%2,%3}, [%4];"
                 : "=r"(r[0]), "=r"(r[1]), "=r"(r[2]), "=r"(r[3]) : "r"(addr));
}

__device__ __forceinline__ void mma16816(float* d, const uint32_t* a,
                                         const uint32_t* b) {
    asm volatile(
        "mma.sync.aligned.m16n8k16.row.col.f32.f16.f16.f32 "
        "{%0,%1,%2,%3}, {%4,%5,%6,%7}, {%8,%9}, {%0,%1,%2,%3};"
        : "+f"(d[0]), "+f"(d[1]), "+f"(d[2]), "+f"(d[3])
        : "r"(a[0]), "r"(a[1]), "r"(a[2]), "r"(a[3]), "r"(b[0]), "r"(b[1]));
}

__device__ __forceinline__ float ftanh(float x) {
    float e = __expf(2.f * x);
    return 1.f - 2.f / (e + 1.f);
}

// ---------------- split-fp16 mma machinery -----------------------------------
template<int NT>
__device__ __forceinline__ void stage_load(
    uint32_t sbase,
    const __half* __restrict__ Ah, const __half* __restrict__ Al, int lda,
    const __half* __restrict__ Bh, const __half* __restrict__ Bl, int ldb,
    int tid, int kof)
{
#pragma unroll
    for (int i = 0; i < 2; ++i) {           // A: 128 rows x 32 k (hi & lo)
        int idx = tid + 256 * i;
        int r = idx >> 2, c = idx & 3;
        uint32_t d = sbase + r * PADROW + c * 16;
        size_t go = (size_t)r * lda + kof + c * 8;
        cp16(d, Ah + go);
        cp16(d + SM_ALO, Al + go);
    }
#pragma unroll
    for (int i = 0; i < 4; ++i) {           // B: 256 rows x 32 k
        int idx = tid + 256 * i;
        int r = idx >> 2, c = idx & 3;
        uint32_t d = sbase + SM_BH + r * PADROW + c * 16;
        size_t go = (size_t)r * ldb + kof + c * 8;
        cp16(d, Bh + go);
        if (NT == 3) cp16(d + SM_BLO, Bl + go);
    }
}

template<int NT>
__device__ __forceinline__ void stage_compute(uint32_t sbase, int lane,
                                              int wm, int wn,
                                              float (&acc)[4][8][4])
{
    const uint32_t a_row = wm * 64 + (lane & 7) + ((lane >> 3) & 1) * 8;
    const uint32_t a_colb = (lane >> 4) * 16;
    const uint32_t b_row = wn * 64 + (lane & 7) + ((lane >> 4) & 1) * 8;
    const uint32_t b_colb = ((lane >> 3) & 1) * 16;
#pragma unroll
    for (int kk = 0; kk < 2; ++kk) {
        uint32_t ahi[4][4], alo[4][4], bfr[4][4];
        const uint32_t ka = sbase + a_row * PADROW + a_colb + kk * 32;
#pragma unroll
        for (int mt = 0; mt < 4; ++mt) {
            ldmx4(ahi[mt], ka + mt * 16 * PADROW);
            ldmx4(alo[mt], ka + mt * 16 * PADROW + SM_ALO);
        }
        const uint32_t kb = sbase + SM_BH + b_row * PADROW + b_colb + kk * 32;
#pragma unroll
        for (int np = 0; np < 4; ++np) ldmx4(bfr[np], kb + np * 16 * PADROW);
#pragma unroll
        for (int mt = 0; mt < 4; ++mt)
#pragma unroll
            for (int np = 0; np < 4; ++np) {
                mma16816(acc[mt][np * 2],     ahi[mt], &bfr[np][0]);
                mma16816(acc[mt][np * 2 + 1], ahi[mt], &bfr[np][2]);
                mma16816(acc[mt][np * 2],     alo[mt], &bfr[np][0]);
                mma16816(acc[mt][np * 2 + 1], alo[mt], &bfr[np][2]);
            }
        if (NT == 3) {
#pragma unroll
            for (int np = 0; np < 4; ++np)
                ldmx4(bfr[np], kb + np * 16 * PADROW + SM_BLO);
#pragma unroll
            for (int mt = 0; mt < 4; ++mt)
#pragma unroll
                for (int np = 0; np < 4; ++np) {
                    mma16816(acc[mt][np * 2],     ahi[mt], &bfr[np][0]);
                    mma16816(acc[mt][np * 2 + 1], ahi[mt], &bfr[np][2]);
                }
        }
    }
}

template<int NT>
__device__ __forceinline__ void gemm_mainloop(
    const __half* Ah, const __half* Al, int lda,
    const __half* Bh, const __half* Bl, int ldb,
    int KT, uint32_t sm0, int tid, float (&acc)[4][8][4])
{
    constexpr uint32_t STG = (NT == 3) ? STAGE3 : STAGE2;
    const int lane = tid & 31, wid = tid >> 5;
    const int wm = wid >> 2, wn = wid & 3;
    stage_load<NT>(sm0, Ah, Al, lda, Bh, Bl, ldb, tid, 0);
    CP_COMMIT();
    stage_load<NT>(sm0 + STG, Ah, Al, lda, Bh, Bl, ldb, tid, 32);
    CP_COMMIT();
    int sl = 2, sc = 0;
    for (int it = 0; it < KT; ++it) {
        CP_WAIT(1);
        __syncthreads();
        if (it + 2 < KT)
            stage_load<NT>(sm0 + sl * STG, Ah, Al, lda, Bh, Bl, ldb,
                           tid, (it + 2) * 32);
        CP_COMMIT();
        stage_compute<NT>(sm0 + sc * STG, lane, wm, wn, acc);
        if (++sl == 3) sl = 0;
        if (++sc == 3) sc = 0;
    }
}

// ---------------- fp32 -> fp16 hi/lo split conversions -----------------------
__global__ void conv_split(const float4* __restrict__ src,
                           __half2* __restrict__ hi,
                           __half2* __restrict__ lo) {
    size_t i = (size_t)blockIdx.x * blockDim.x + threadIdx.x;
    float4 v = src[i];
    __half2 h0 = __floats2half2_rn(v.x, v.y);
    __half2 h1 = __floats2half2_rn(v.z, v.w);
    float2 f0 = __half22float2(h0);
    float2 f1 = __half22float2(h1);
    hi[i * 2 + 0] = h0;
    hi[i * 2 + 1] = h1;
    lo[i * 2 + 0] = __floats2half2_rn(v.x - f0.x, v.y - f0.y);
    lo[i * 2 + 1] = __floats2half2_rn(v.z - f1.x, v.w - f1.y);
}

// gather attn_w[:, H:3H] -> g_w_hi [HDIM x KEO] (hi only; 2-term attn)
__global__ void conv_w_kernel(const float* __restrict__ attn_w) {
    int n = blockIdx.x;
    const float2* src = (const float2*)(attn_w + (size_t)n * 3 * HDIM + HDIM);
    __half2* hi = (__half2*)(g_w_hi + (size_t)n * KEO);
    for (int c = threadIdx.x; c < KEO / 2; c += blockDim.x) {
        float2 v = src[c];
        hi[c] = __floats2half2_rn(v.x, v.y);
    }
}

// [w_ih | w_hh] rows -> g_wg_hi [NG x KCAT] (hi only; 2-term gates)
__global__ void conv_wg_kernel(const float* __restrict__ w_ih,
                               const float* __restrict__ w_hh) {
    int n = blockIdx.x;
    for (int k = threadIdx.x; k < KCAT; k += blockDim.x) {
        float v = (k < KX) ? w_ih[(size_t)n * KX + k]
                           : w_hh[(size_t)n * HDIM + (k - KX)];
        g_wg_hi[(size_t)n * KCAT + k] = __float2half_rn(v);
    }
}

// [x | h0] rows -> g_xh hi/lo [BS x KCAT]
__global__ void conv_xh_kernel(const float* __restrict__ h0) {
    int b = blockIdx.x;
    for (int k = threadIdx.x; k < KCAT; k += blockDim.x) {
        float v = (k < KX) ? g_x[(size_t)b * KX + k]
                           : h0[(size_t)b * HDIM + (k - KX)];
        __half h = __float2half_rn(v);
        g_xh_hi[(size_t)b * KCAT + k] = h;
        g_xh_lo[(size_t)b * KCAT + k] = __float2half_rn(v - __half2float(h));
    }
}

// ---------------- embedding gather ------------------------------------------
__global__ void embed_kernel(const int* __restrict__ tok,
                             const float* __restrict__ emb_w) {
    int b = blockIdx.x;
    int t = tok[b];
    for (int e = threadIdx.x; e < EDIM; e += blockDim.x) {
        float v = emb_w[(size_t)t * EDIM + e];
        g_x[(size_t)b * KX + e] = v;
        g_cat[(size_t)b * KCAT + 3 * HDIM + e] = v;
    }
}

// ---------------- SIMT GEMM (h_proj only) ------------------------------------
__global__ __launch_bounds__(NTHREADS)
void gemm_tn(const float* __restrict__ A, int lda,
             const float* __restrict__ B, int ldb,
             float* __restrict__ C, int ldc, int K) {
    __shared__ float As[TBK][TBM];
    __shared__ float Bs[TBK][TBN];
    const int tid = threadIdx.x;
    const int col0 = blockIdx.x * TBN;
    const int tm0 = (tid >> 4) * 8;
    const int tn0 = (tid & 15) * 4;
    float acc[8][4] = {};
    for (int k0 = 0; k0 < K; k0 += TBK) {
#pragma unroll
        for (int t = 0; t < 2; ++t) {
            int lin = (tid + t * NTHREADS) * 4;
            int r = lin >> 4, cc = lin & 15;
            float4 v = *(const float4*)(A + (size_t)r * lda + k0 + cc);
            As[cc + 0][r] = v.x; As[cc + 1][r] = v.y;
            As[cc + 2][r] = v.z; As[cc + 3][r] = v.w;
        }
        {
            int lin = tid * 4;
            int r = lin >> 4, cc = lin & 15;
            float4 v = *(const float4*)(B + (size_t)(col0 + r) * ldb + k0 + cc);
            Bs[cc + 0][r] = v.x; Bs[cc + 1][r] = v.y;
            Bs[cc + 2][r] = v.z; Bs[cc + 3][r] = v.w;
        }
        __syncthreads();
#pragma unroll
        for (int k = 0; k < TBK; ++k) {
            float4 a0 = *(const float4*)&As[k][tm0];
            float4 a1 = *(const float4*)&As[k][tm0 + 4];
            float4 b0 = *(const float4*)&Bs[k][tn0];
            float a[8] = {a0.x, a0.y, a0.z, a0.w, a1.x, a1.y, a1.z, a1.w};
            float b[4] = {b0.x, b0.y, b0.z, b0.w};
#pragma unroll
            for (int i = 0; i < 8; ++i)
#pragma unroll
                for (int j = 0; j < 4; ++j)
                    acc[i][j] = fmaf(a[i], b[j], acc[i][j]);
        }
        __syncthreads();
    }
#pragma unroll
    for (int i = 0; i < 8; ++i)
#pragma unroll
        for (int j = 0; j < 4; ++j)
            C[(size_t)(tm0 + i) * ldc + col0 + tn0 + j] = acc[i][j];
}

// ================= attention energy: mma + fused tanh/v epilogue =============
// grid 256; each CTA: one 128-row M-tile, 4 N-chunks of 256 over K=2048. 2-term.
__global__ __launch_bounds__(256, 1)
void attn_mma(const float* __restrict__ attn_b, const float* __restrict__ v_w) {
    extern __shared__ char dsm[];
    __shared__ float base_sh[256], v_sh[256], red[4][128];
    const uint32_t sm0 = smem_u32(dsm);
    const int tid = threadIdx.x, lane = tid & 31, wid = tid >> 5;
    const int wm = wid >> 2, wn = wid & 3;
    const int row0 = blockIdx.x * 128;
    const int b_idx = row0 >> 8;

    float rowpart[4][2] = {};
    for (int ch = 0; ch < 4; ++ch) {
        const int n0 = ch * 256;
        __syncthreads();
        base_sh[tid] = g_hproj[(size_t)b_idx * HDIM + n0 + tid] + attn_b[n0 + tid];
        v_sh[tid] = v_w[n0 + tid];
        float acc[4][8][4] = {};
        gemm_mainloop<2>(g_eo_hi + (size_t)row0 * KEO,
                         g_eo_lo + (size_t)row0 * KEO, KEO,
                         g_w_hi + (size_t)n0 * KEO,
                         g_w_hi + (size_t)n0 * KEO, KEO,
                         64, sm0, tid, acc);
#pragma unroll
        for (int mt = 0; mt < 4; ++mt)
#pragma unroll
            for (int nt = 0; nt < 8; ++nt) {
                int nb = wn * 64 + nt * 8 + (lane & 3) * 2;
                float b0 = base_sh[nb], b1 = base_sh[nb + 1];
                float v0 = v_sh[nb], v1 = v_sh[nb + 1];
                rowpart[mt][0] += v0 * ftanh(acc[mt][nt][0] + b0)
                                + v1 * ftanh(acc[mt][nt][1] + b1);
                rowpart[mt][1] += v0 * ftanh(acc[mt][nt][2] + b0)
                                + v1 * ftanh(acc[mt][nt][3] + b1);
            }
    }
#pragma unroll
    for (int mt = 0; mt < 4; ++mt)
#pragma unroll
        for (int h = 0; h < 2; ++h) {
            float v = rowpart[mt][h];
            v += __shfl_xor_sync(0xffffffff, v, 1);
            v += __shfl_xor_sync(0xffffffff, v, 2);
            if ((lane & 3) == 0)
                red[wn][wm * 64 + mt * 16 + (lane >> 2) + 8 * h] = v;
        }
    __syncthreads();
    if (tid < 128)
        g_score[row0 + tid] = red[0][tid] + red[1][tid] + red[2][tid] + red[3][tid];
}

// ================= fc: prediction = cat @ fco^T + b (3-term) =================
__global__ __launch_bounds__(256, 1)
void fc_mma(const float* __restrict__ fco_b, float* __restrict__ out) {
    extern __shared__ char dsm[];
    const uint32_t sm0 = smem_u32(dsm);
    const int tid = threadIdx.x, lane = tid & 31, wid = tid >> 5;
    const int wm = wid >> 2, wn = wid & 3;
    const int n0 = blockIdx.x * 256;
    float acc[4][8][4] = {};
    gemm_mainloop<3>(g_cat_hi, g_cat_lo, KCAT,
                     g_fco_hi + (size_t)n0 * KCAT,
                     g_fco_lo + (size_t)n0 * KCAT, KCAT,
                     KCAT / 32, sm0, tid, acc);
#pragma unroll
    for (int mt = 0; mt < 4; ++mt) {
        int r0 = wm * 64 + mt * 16 + (lane >> 2);
#pragma unroll
        for (int nt = 0; nt < 8; ++nt) {
            int n = n0 + wn * 64 + nt * 8 + (lane & 3) * 2;
            float b0 = fco_b[n], b1 = fco_b[n + 1];
            out[(size_t)r0 * VDIM + n] = acc[mt][nt][0] + b0;
            out[(size_t)r0 * VDIM + n + 1] = acc[mt][nt][1] + b1;
            out[(size_t)(r0 + 8) * VDIM + n] = acc[mt][nt][2] + b0;
            out[(size_t)(r0 + 8) * VDIM + n + 1] = acc[mt][nt][3] + b1;
        }
    }
}

// ================= gates: [x|h] @ [w_ih|w_hh]^T, split-K=2, 2-term ===========
__global__ __launch_bounds__(256, 1)
void gates_mma() {
    extern __shared__ char dsm[];
    const uint32_t sm0 = smem_u32(dsm);
    const int tid = threadIdx.x, lane = tid & 31, wid = tid >> 5;
    const int wm = wid >> 2, wn = wid & 3;
    const int n0 = (blockIdx.x & 15) * 256;
    const int ks = blockIdx.x >> 4;
    const int kof = ks * (KCAT / 2);
    float acc[4][8][4] = {};
    gemm_mainloop<2>(g_xh_hi + kof, g_xh_lo + kof, KCAT,
                     g_wg_hi + (size_t)n0 * KCAT + kof,
                     g_wg_hi + (size_t)n0 * KCAT + kof, KCAT,
                     KCAT / 64, sm0, tid, acc);
    float* gp = g_gatesp[ks];
#pragma unroll
    for (int mt = 0; mt < 4; ++mt) {
        int r0 = wm * 64 + mt * 16 + (lane >> 2);
#pragma unroll
        for (int nt = 0; nt < 8; ++nt) {
            int n = n0 + wn * 64 + nt * 8 + (lane & 3) * 2;
            gp[(size_t)r0 * NG + n] = acc[mt][nt][0];
            gp[(size_t)r0 * NG + n + 1] = acc[mt][nt][1];
            gp[(size_t)(r0 + 8) * NG + n] = acc[mt][nt][2];
            gp[(size_t)(r0 + 8) * NG + n + 1] = acc[mt][nt][3];
        }
    }
}

// ---------------- softmax over seq -------------------------------------------
__global__ void softmax_kernel() {
    __shared__ float sred[SLEN];
    int b = blockIdx.x, s = threadIdx.x;
    float sc = g_score[b * SLEN + s];
    sred[s] = sc; __syncthreads();
    for (int o = SLEN / 2; o > 0; o >>= 1) {
        if (s < o) sred[s] = fmaxf(sred[s], sred[s + o]);
        __syncthreads();
    }
    float m = sred[0]; __syncthreads();
    float e = expf(sc - m);
    sred[s] = e; __syncthreads();
    for (int o = SLEN / 2; o > 0; o >>= 1) {
        if (s < o) sred[s] += sred[s + o];
        __syncthreads();
    }
    g_attn[b * SLEN + s] = e / sred[0];
}

// ---------------- weighted = a @ eo ------------------------------------------
__global__ void weighted_kernel(const float* __restrict__ eo) {
    __shared__ float a_sh[SLEN];
    int b = blockIdx.y;
    int d = blockIdx.x * 256 + threadIdx.x;
    if (threadIdx.x < SLEN) a_sh[threadIdx.x] = g_attn[b * SLEN + threadIdx.x];
    __syncthreads();
    const float* eob = eo + (size_t)b * SLEN * KEO + d;
    float acc = 0.f;
#pragma unroll 8
    for (int s = 0; s < SLEN; ++s) acc = fmaf(a_sh[s], eob[(size_t)s * KEO], acc);
    g_x[(size_t)b * KX + EDIM + d] = acc;
    g_cat[(size_t)b * KCAT + HDIM + d] = acc;
}

// ---------------- LSTM cell elementwise --------------------------------------
__global__ void lstm_kernel(const float* __restrict__ c0,
                            const float* __restrict__ b_ih,
                            const float* __restrict__ b_hh,
                            float* __restrict__ out) {
    int idx = blockIdx.x * blockDim.x + threadIdx.x;   // [0, 128*1024)
    int b = idx >> 10, h = idx & 1023;
    const float* g0 = g_gatesp[0] + (size_t)b * NG;
    const float* g1 = g_gatesp[1] + (size_t)b * NG;
    float ig = g0[h]            + g1[h]            + b_ih[h]            + b_hh[h];
    float fg = g0[HDIM + h]     + g1[HDIM + h]     + b_ih[HDIM + h]     + b_hh[HDIM + h];
    float gg = g0[2 * HDIM + h] + g1[2 * HDIM + h] + b_ih[2 * HDIM + h] + b_hh[2 * HDIM + h];
    float og = g0[3 * HDIM + h] + g1[3 * HDIM + h] + b_ih[3 * HDIM + h] + b_hh[3 * HDIM + h];
    float si = 1.f / (1.f + expf(-ig));
    float sf = 1.f / (1.f + expf(-fg));
    float so = 1.f / (1.f + expf(-og));
    float cn = sf * c0[idx] + si * tanhf(gg);
    float hn = so * tanhf(cn);
    g_cat[(size_t)b * KCAT + h] = hn;
    out[(size_t)BS * VDIM + idx] = hn;                  // h_new
    out[(size_t)BS * VDIM + BS * HDIM + idx] = cn;      // c_new
}

// ---------------- launch -----------------------------------------------------
extern "C" void kernel_launch(void* const* d_in, const int* in_sizes, int n_in,
                              void* d_out, int out_size) {
    const int*   inp_tok = (const int*)  d_in[0];
    const float* h0      = (const float*)d_in[1];
    const float* c0      = (const float*)d_in[2];
    const float* eo      = (const float*)d_in[3];
    const float* emb_w   = (const float*)d_in[4];
    const float* attn_w  = (const float*)d_in[5];
    const float* attn_b  = (const float*)d_in[6];
    const float* v_w     = (const float*)d_in[7];
    const float* w_ih    = (const float*)d_in[8];
    const float* w_hh    = (const float*)d_in[9];
    const float* b_ih    = (const float*)d_in[10];
    const float* b_hh    = (const float*)d_in[11];
    const float* fco_w   = (const float*)d_in[12];
    const float* fco_b   = (const float*)d_in[13];
    float* out = (float*)d_out;

    float* p_hproj;
    cudaGetSymbolAddress((void**)&p_hproj, g_hproj);
    void *p_eo_hi, *p_eo_lo, *p_fco_hi, *p_fco_lo, *p_cat, *p_cat_hi, *p_cat_lo;
    cudaGetSymbolAddress(&p_eo_hi,  g_eo_hi);
    cudaGetSymbolAddress(&p_eo_lo,  g_eo_lo);
    cudaGetSymbolAddress(&p_fco_hi, g_fco_hi);
    cudaGetSymbolAddress(&p_fco_lo, g_fco_lo);
    cudaGetSymbolAddress(&p_cat,    g_cat);
    cudaGetSymbolAddress(&p_cat_hi, g_cat_hi);
    cudaGetSymbolAddress(&p_cat_lo, g_cat_lo);

    cudaFuncSetAttribute(attn_mma,  cudaFuncAttributeMaxDynamicSharedMemorySize, DSMEM2);
    cudaFuncSetAttribute(gates_mma, cudaFuncAttributeMaxDynamicSharedMemorySize, DSMEM2);
    cudaFuncSetAttribute(fc_mma,    cudaFuncAttributeMaxDynamicSharedMemorySize, DSMEM3);

    // conversions
    conv_split<<<(ROWS * (size_t)KEO) / 4 / 256, 256>>>(
        (const float4*)eo, (__half2*)p_eo_hi, (__half2*)p_eo_lo);
    conv_w_kernel<<<HDIM, 256>>>(attn_w);
    conv_split<<<((size_t)VDIM * KCAT) / 4 / 256, 256>>>(
        (const float4*)fco_w, (__half2*)p_fco_hi, (__half2*)p_fco_lo);
    conv_wg_kernel<<<NG, 256>>>(w_ih, w_hh);

    // embedding + h_proj
    embed_kernel<<<BS, 256>>>(inp_tok, emb_w);
    gemm_tn<<<HDIM / TBN, NTHREADS>>>(h0, HDIM, attn_w, 3 * HDIM,
                                      p_hproj, HDIM, HDIM);

    // attention scores (fused GEMM + tanh + v-dot)
    attn_mma<<<256, 256, DSMEM2>>>(attn_b, v_w);
    softmax_kernel<<<BS, SLEN>>>();
    weighted_kernel<<<dim3(KEO / 256, BS), 256>>>(eo);

    // LSTM gates
    conv_xh_kernel<<<BS, 256>>>(h0);
    gates_mma<<<32, 256, DSMEM2>>>();
    lstm_kernel<<<(BS * HDIM) / 256, 256>>>(c0, b_ih, b_hh, out);

    // output projection
    conv_split<<<((size_t)BS * KCAT) / 4 / 256, 256>>>(
        (const float4*)p_cat, (__half2*)p_cat_hi, (__half2*)p_cat_lo);
    fc_mma<<<VDIM / 256, 256, DSMEM3>>>(fco_b, out);
}

// round 6
// speedup vs baseline: 3.5850x; 1.2681x over previous
#include <cuda_runtime.h>
#include <cuda_fp16.h>
#include <cstdint>
#include <math.h>

// Problem dims
#define BS   128
#define SLEN 256
#define EDIM 512
#define HDIM 1024
#define VDIM 32000
#define ROWS (BS * SLEN)        // 32768
#define KEO  (2 * HDIM)         // 2048
#define KX   (EDIM + 2 * HDIM)  // 2560
#define KCAT (3 * HDIM + EDIM)  // 3584
#define NG   (4 * HDIM)         // 4096

// SIMT GEMM tile config (h_proj only)
#define TBM 128
#define TBN 64
#define TBK 16
#define NTHREADS 256

// mma.sync tile: CTA 256 thr, tile 128(M) x 256(N), k-step 32
#define PADROW 80               // bytes per 32-half row - conflict-free ldmatrix
#define SM_ALO 10240            // A_lo offset inside stage (NT>=2)
#define SM_BH  20480            // B offset for NT>=2
#define SM_BLO 20480            // B_lo offset relative to B_hi (NT==3)
#define STAGE1 30720
#define STAGE2 40960
#define STAGE3 61440
#define DSMEM1 (3 * STAGE1)     // 92160  (attn, 3-stage)
#define DSMEM2 (3 * STAGE2)     // 122880 (gates, 3-stage)
#define DSMEMF (2 * STAGE3)     // 122880 (fc, 2-stage w/ in-kernel conv)

// ---------------- scratch (device globals; no allocation allowed) ------------
__device__ float g_hproj[BS * HDIM];
__device__ float g_score[ROWS];
__device__ float g_attn[BS * SLEN];
__device__ float g_x[BS * KX];
__device__ float g_cat[BS * KCAT];
__device__ float g_gatesp[2][BS * NG];
__device__ __align__(16) __half g_eo_hi[(size_t)ROWS * KEO];
__device__ __align__(16) __half g_w_hi[(size_t)HDIM * KEO];
__device__ __align__(16) __half g_cat_hi[(size_t)BS * KCAT];
__device__ __align__(16) __half g_cat_lo[(size_t)BS * KCAT];
__device__ __align__(16) __half g_xh_hi[(size_t)BS * KCAT];
__device__ __align__(16) __half g_xh_lo[(size_t)BS * KCAT];
__device__ __align__(16) __half g_wg_hi[(size_t)NG * KCAT];

// ---------------- PTX helpers ------------------------------------------------
__device__ __forceinline__ uint32_t smem_u32(const void* p) {
    uint32_t a;
    asm("{ .reg .u64 t; cvta.to.shared.u64 t, %1; cvt.u32.u64 %0, t; }"
        : "=r"(a) : "l"(p));
    return a;
}

__device__ __forceinline__ void cp16(uint32_t dst, const void* src) {
    asm volatile("cp.async.cg.shared.global [%0], [%1], 16;"
                 :: "r"(dst), "l"(src) : "memory");
}
#define CP_COMMIT() asm volatile("cp.async.commit_group;" ::: "memory")
#define CP_WAIT(n)  asm volatile("cp.async.wait_group %0;" :: "n"(n) : "memory")

__device__ __forceinline__ void ldmx4(uint32_t* r, uint32_t addr) {
    asm volatile("ldmatrix.sync.aligned.m8n8.x4.shared.b16 {%0,%1,%2,%3}, [%4];"
                 : "=r"(r[0]), "=r"(r[1]), "=r"(r[2]), "=r"(r[3]) : "r"(addr));
}

__device__ __forceinline__ void sts128(uint32_t addr, uint32_t a, uint32_t b,
                                       uint32_t c, uint32_t d) {
    asm volatile("st.shared.v4.b32 [%0], {%1,%2,%3,%4};"
                 :: "r"(addr), "r"(a), "r"(b), "r"(c), "r"(d) : "memory");
}

__device__ __forceinline__ uint32_t h2u(__half2 h) {
    return *reinterpret_cast<uint32_t*>(&h);
}

__device__ __forceinline__ void mma16816(float* d, const uint32_t* a,
                                         const uint32_t* b) {
    asm volatile(
        "mma.sync.aligned.m16n8k16.row.col.f32.f16.f16.f32 "
        "{%0,%1,%2,%3}, {%4,%5,%6,%7}, {%8,%9}, {%0,%1,%2,%3};"
        : "+f"(d[0]), "+f"(d[1]), "+f"(d[2]), "+f"(d[3])
        : "r"(a[0]), "r"(a[1]), "r"(a[2]), "r"(a[3]), "r"(b[0]), "r"(b[1]));
}

__device__ __forceinline__ float ftanh(float x) {
    float e = __expf(2.f * x);
    return 1.f - 2.f / (e + 1.f);
}

// ---------------- split-fp16 mma machinery -----------------------------------
// NT=1: A hi, B hi. NT=2: A hi+lo, B hi. NT=3: A hi+lo, B hi+lo.
template<int NT>
__device__ __forceinline__ void stage_load(
    uint32_t sbase,
    const __half* __restrict__ Ah, const __half* __restrict__ Al, int lda,
    const __half* __restrict__ Bh, const __half* __restrict__ Bl, int ldb,
    int tid, int kof)
{
    constexpr uint32_t BOFF = (NT == 1) ? 10240 : SM_BH;
#pragma unroll
    for (int i = 0; i < 2; ++i) {           // A: 128 rows x 32 k
        int idx = tid + 256 * i;
        int r = idx >> 2, c = idx & 3;
        uint32_t d = sbase + r * PADROW + c * 16;
        size_t go = (size_t)r * lda + kof + c * 8;
        cp16(d, Ah + go);
        if (NT >= 2) cp16(d + SM_ALO, Al + go);
    }
#pragma unroll
    for (int i = 0; i < 4; ++i) {           // B: 256 rows x 32 k
        int idx = tid + 256 * i;
        int r = idx >> 2, c = idx & 3;
        uint32_t d = sbase + BOFF + r * PADROW + c * 16;
        size_t go = (size_t)r * ldb + kof + c * 8;
        cp16(d, Bh + go);
        if (NT == 3) cp16(d + SM_BLO, Bl + go);
    }
}

template<int NT>
__device__ __forceinline__ void stage_compute(uint32_t sbase, int lane,
                                              int wm, int wn,
                                              float (&acc)[4][8][4])
{
    constexpr uint32_t BOFF = (NT == 1) ? 10240 : SM_BH;
    const uint32_t a_row = wm * 64 + (lane & 7) + ((lane >> 3) & 1) * 8;
    const uint32_t a_colb = (lane >> 4) * 16;
    const uint32_t b_row = wn * 64 + (lane & 7) + ((lane >> 4) & 1) * 8;
    const uint32_t b_colb = ((lane >> 3) & 1) * 16;
#pragma unroll
    for (int kk = 0; kk < 2; ++kk) {
        uint32_t ahi[4][4], alo[4][4], bfr[4][4];
        const uint32_t ka = sbase + a_row * PADROW + a_colb + kk * 32;
#pragma unroll
        for (int mt = 0; mt < 4; ++mt) {
            ldmx4(ahi[mt], ka + mt * 16 * PADROW);
            if (NT >= 2) ldmx4(alo[mt], ka + mt * 16 * PADROW + SM_ALO);
        }
        const uint32_t kb = sbase + BOFF + b_row * PADROW + b_colb + kk * 32;
#pragma unroll
        for (int np = 0; np < 4; ++np) ldmx4(bfr[np], kb + np * 16 * PADROW);
#pragma unroll
        for (int mt = 0; mt < 4; ++mt)
#pragma unroll
            for (int np = 0; np < 4; ++np) {
                mma16816(acc[mt][np * 2],     ahi[mt], &bfr[np][0]);
                mma16816(acc[mt][np * 2 + 1], ahi[mt], &bfr[np][2]);
                if (NT >= 2) {
                    mma16816(acc[mt][np * 2],     alo[mt], &bfr[np][0]);
                    mma16816(acc[mt][np * 2 + 1], alo[mt], &bfr[np][2]);
                }
            }
        if (NT == 3) {
#pragma unroll
            for (int np = 0; np < 4; ++np)
                ldmx4(bfr[np], kb + np * 16 * PADROW + SM_BLO);
#pragma unroll
            for (int mt = 0; mt < 4; ++mt)
#pragma unroll
                for (int np = 0; np < 4; ++np) {
                    mma16816(acc[mt][np * 2],     ahi[mt], &bfr[np][0]);
                    mma16816(acc[mt][np * 2 + 1], ahi[mt], &bfr[np][2]);
                }
        }
    }
}

template<int NT>
__device__ __forceinline__ void gemm_mainloop(
    const __half* Ah, const __half* Al, int lda,
    const __half* Bh, const __half* Bl, int ldb,
    int KT, uint32_t sm0, int tid, float (&acc)[4][8][4])
{
    constexpr uint32_t STG = (NT == 1) ? STAGE1 : ((NT == 2) ? STAGE2 : STAGE3);
    const int lane = tid & 31, wid = tid >> 5;
    const int wm = wid >> 2, wn = wid & 3;
    stage_load<NT>(sm0, Ah, Al, lda, Bh, Bl, ldb, tid, 0);
    CP_COMMIT();
    stage_load<NT>(sm0 + STG, Ah, Al, lda, Bh, Bl, ldb, tid, 32);
    CP_COMMIT();
    int sl = 2, sc = 0;
    for (int it = 0; it < KT; ++it) {
        CP_WAIT(1);
        __syncthreads();
        if (it + 2 < KT)
            stage_load<NT>(sm0 + sl * STG, Ah, Al, lda, Bh, Bl, ldb,
                           tid, (it + 2) * 32);
        CP_COMMIT();
        stage_compute<NT>(sm0 + sc * STG, lane, wm, wn, acc);
        if (++sl == 3) sl = 0;
        if (++sc == 3) sc = 0;
    }
}

// ---------------- conversions -------------------------------------------------
__global__ void conv_hi(const float4* __restrict__ src,
                        __half2* __restrict__ hi) {
    size_t i = (size_t)blockIdx.x * blockDim.x + threadIdx.x;
    float4 v = src[i];
    hi[i * 2 + 0] = __floats2half2_rn(v.x, v.y);
    hi[i * 2 + 1] = __floats2half2_rn(v.z, v.w);
}

__global__ void conv_split(const float4* __restrict__ src,
                           __half2* __restrict__ hi,
                           __half2* __restrict__ lo) {
    size_t i = (size_t)blockIdx.x * blockDim.x + threadIdx.x;
    float4 v = src[i];
    __half2 h0 = __floats2half2_rn(v.x, v.y);
    __half2 h1 = __floats2half2_rn(v.z, v.w);
    float2 f0 = __half22float2(h0);
    float2 f1 = __half22float2(h1);
    hi[i * 2 + 0] = h0;
    hi[i * 2 + 1] = h1;
    lo[i * 2 + 0] = __floats2half2_rn(v.x - f0.x, v.y - f0.y);
    lo[i * 2 + 1] = __floats2half2_rn(v.z - f1.x, v.w - f1.y);
}

// gather attn_w[:, H:3H] -> g_w_hi [HDIM x KEO]
__global__ void conv_w_kernel(const float* __restrict__ attn_w) {
    int n = blockIdx.x;
    const float2* src = (const float2*)(attn_w + (size_t)n * 3 * HDIM + HDIM);
    __half2* hi = (__half2*)(g_w_hi + (size_t)n * KEO);
    for (int c = threadIdx.x; c < KEO / 2; c += blockDim.x) {
        float2 v = src[c];
        hi[c] = __floats2half2_rn(v.x, v.y);
    }
}

// [w_ih | w_hh] rows -> g_wg_hi [NG x KCAT]
__global__ void conv_wg_kernel(const float* __restrict__ w_ih,
                               const float* __restrict__ w_hh) {
    int n = blockIdx.x;
    for (int k = threadIdx.x; k < KCAT; k += blockDim.x) {
        float v = (k < KX) ? w_ih[(size_t)n * KX + k]
                           : w_hh[(size_t)n * HDIM + (k - KX)];
        g_wg_hi[(size_t)n * KCAT + k] = __float2half_rn(v);
    }
}

// [x | h0] rows -> g_xh hi/lo [BS x KCAT]
__global__ void conv_xh_kernel(const float* __restrict__ h0) {
    int b = blockIdx.x;
    for (int k = threadIdx.x; k < KCAT; k += blockDim.x) {
        float v = (k < KX) ? g_x[(size_t)b * KX + k]
                           : h0[(size_t)b * HDIM + (k - KX)];
        __half h = __float2half_rn(v);
        g_xh_hi[(size_t)b * KCAT + k] = h;
        g_xh_lo[(size_t)b * KCAT + k] = __float2half_rn(v - __half2float(h));
    }
}

// ---------------- embedding gather ------------------------------------------
__global__ void embed_kernel(const int* __restrict__ tok,
                             const float* __restrict__ emb_w) {
    int b = blockIdx.x;
    int t = tok[b];
    for (int e = threadIdx.x; e < EDIM; e += blockDim.x) {
        float v = emb_w[(size_t)t * EDIM + e];
        g_x[(size_t)b * KX + e] = v;
        g_cat[(size_t)b * KCAT + 3 * HDIM + e] = v;
    }
}

// ---------------- SIMT GEMM (h_proj only) ------------------------------------
__global__ __launch_bounds__(NTHREADS)
void gemm_tn(const float* __restrict__ A, int lda,
             const float* __restrict__ B, int ldb,
             float* __restrict__ C, int ldc, int K) {
    __shared__ float As[TBK][TBM];
    __shared__ float Bs[TBK][TBN];
    const int tid = threadIdx.x;
    const int col0 = blockIdx.x * TBN;
    const int tm0 = (tid >> 4) * 8;
    const int tn0 = (tid & 15) * 4;
    float acc[8][4] = {};
    for (int k0 = 0; k0 < K; k0 += TBK) {
#pragma unroll
        for (int t = 0; t < 2; ++t) {
            int lin = (tid + t * NTHREADS) * 4;
            int r = lin >> 4, cc = lin & 15;
            float4 v = *(const float4*)(A + (size_t)r * lda + k0 + cc);
            As[cc + 0][r] = v.x; As[cc + 1][r] = v.y;
            As[cc + 2][r] = v.z; As[cc + 3][r] = v.w;
        }
        {
            int lin = tid * 4;
            int r = lin >> 4, cc = lin & 15;
            float4 v = *(const float4*)(B + (size_t)(col0 + r) * ldb + k0 + cc);
            Bs[cc + 0][r] = v.x; Bs[cc + 1][r] = v.y;
            Bs[cc + 2][r] = v.z; Bs[cc + 3][r] = v.w;
        }
        __syncthreads();
#pragma unroll
        for (int k = 0; k < TBK; ++k) {
            float4 a0 = *(const float4*)&As[k][tm0];
            float4 a1 = *(const float4*)&As[k][tm0 + 4];
            float4 b0 = *(const float4*)&Bs[k][tn0];
            float a[8] = {a0.x, a0.y, a0.z, a0.w, a1.x, a1.y, a1.z, a1.w};
            float b[4] = {b0.x, b0.y, b0.z, b0.w};
#pragma unroll
            for (int i = 0; i < 8; ++i)
#pragma unroll
                for (int j = 0; j < 4; ++j)
                    acc[i][j] = fmaf(a[i], b[j], acc[i][j]);
        }
        __syncthreads();
    }
#pragma unroll
    for (int i = 0; i < 8; ++i)
#pragma unroll
        for (int j = 0; j < 4; ++j)
            C[(size_t)(tm0 + i) * ldc + col0 + tn0 + j] = acc[i][j];
}

// ================= attention energy: 1-term fp16 mma + fused epilogue ========
__global__ __launch_bounds__(256, 1)
void attn_mma(const float* __restrict__ attn_b, const float* __restrict__ v_w) {
    extern __shared__ char dsm[];
    __shared__ float base_sh[256], v_sh[256], red[4][128];
    const uint32_t sm0 = smem_u32(dsm);
    const int tid = threadIdx.x, lane = tid & 31, wid = tid >> 5;
    const int wm = wid >> 2, wn = wid & 3;
    const int row0 = blockIdx.x * 128;
    const int b_idx = row0 >> 8;

    float rowpart[4][2] = {};
    for (int ch = 0; ch < 4; ++ch) {
        const int n0 = ch * 256;
        __syncthreads();
        base_sh[tid] = g_hproj[(size_t)b_idx * HDIM + n0 + tid] + attn_b[n0 + tid];
        v_sh[tid] = v_w[n0 + tid];
        float acc[4][8][4] = {};
        gemm_mainloop<1>(g_eo_hi + (size_t)row0 * KEO, nullptr, KEO,
                         g_w_hi + (size_t)n0 * KEO, nullptr, KEO,
                         64, sm0, tid, acc);
#pragma unroll
        for (int mt = 0; mt < 4; ++mt)
#pragma unroll
            for (int nt = 0; nt < 8; ++nt) {
                int nb = wn * 64 + nt * 8 + (lane & 3) * 2;
                float b0 = base_sh[nb], b1 = base_sh[nb + 1];
                float v0 = v_sh[nb], v1 = v_sh[nb + 1];
                rowpart[mt][0] += v0 * ftanh(acc[mt][nt][0] + b0)
                                + v1 * ftanh(acc[mt][nt][1] + b1);
                rowpart[mt][1] += v0 * ftanh(acc[mt][nt][2] + b0)
                                + v1 * ftanh(acc[mt][nt][3] + b1);
            }
    }
#pragma unroll
    for (int mt = 0; mt < 4; ++mt)
#pragma unroll
        for (int h = 0; h < 2; ++h) {
            float v = rowpart[mt][h];
            v += __shfl_xor_sync(0xffffffff, v, 1);
            v += __shfl_xor_sync(0xffffffff, v, 2);
            if ((lane & 3) == 0)
                red[wn][wm * 64 + mt * 16 + (lane >> 2) + 8 * h] = v;
        }
    __syncthreads();
    if (tid < 128)
        g_score[row0 + tid] = red[0][tid] + red[1][tid] + red[2][tid] + red[3][tid];
}

// ================= fc: 3-term, B (fco_w) converted fp32->hi/lo in-kernel =====
__device__ __forceinline__ void load_fc(uint32_t sbase,
                                        const float* __restrict__ fco,
                                        int n0, int kof, int tid) {
    // A: cat hi/lo, 128 rows x 32 k (cp.async; tiny, L2-resident)
#pragma unroll
    for (int i = 0; i < 2; ++i) {
        int idx = tid + 256 * i;
        int r = idx >> 2, c = idx & 3;
        uint32_t d = sbase + r * PADROW + c * 16;
        size_t go = (size_t)r * KCAT + kof + c * 8;
        cp16(d, g_cat_hi + go);
        cp16(d + SM_ALO, g_cat_lo + go);
    }
    // B: row `tid` of 256, 32 fp32 -> hi/lo halves in PADROW layout
    const float4* src = (const float4*)(fco + (size_t)(n0 + tid) * KCAT + kof);
    uint32_t bh = sbase + SM_BH + tid * PADROW;
#pragma unroll
    for (int j = 0; j < 8; j += 2) {
        float4 a = src[j], b = src[j + 1];
        __half2 h0 = __floats2half2_rn(a.x, a.y), h1 = __floats2half2_rn(a.z, a.w);
        __half2 h2 = __floats2half2_rn(b.x, b.y), h3 = __floats2half2_rn(b.z, b.w);
        float2 f0 = __half22float2(h0), f1 = __half22float2(h1);
        float2 f2 = __half22float2(h2), f3 = __half22float2(h3);
        __half2 l0 = __floats2half2_rn(a.x - f0.x, a.y - f0.y);
        __half2 l1 = __floats2half2_rn(a.z - f1.x, a.w - f1.y);
        __half2 l2 = __floats2half2_rn(b.x - f2.x, b.y - f2.y);
        __half2 l3 = __floats2half2_rn(b.z - f3.x, b.w - f3.y);
        sts128(bh + j * 8,          h2u(h0), h2u(h1), h2u(h2), h2u(h3));
        sts128(bh + SM_BLO + j * 8, h2u(l0), h2u(l1), h2u(l2), h2u(l3));
    }
}

__global__ __launch_bounds__(256, 1)
void fc_mma(const float* __restrict__ fco_w, const float* __restrict__ fco_b,
            float* __restrict__ out) {
    extern __shared__ char dsm[];
    const uint32_t sm0 = smem_u32(dsm);
    const int tid = threadIdx.x, lane = tid & 31, wid = tid >> 5;
    const int wm = wid >> 2, wn = wid & 3;
    const int n0 = blockIdx.x * 256;
    float acc[4][8][4] = {};

    load_fc(sm0, fco_w, n0, 0, tid);
    CP_COMMIT();
    load_fc(sm0 + STAGE3, fco_w, n0, 32, tid);
    CP_COMMIT();
    const int KT = KCAT / 32;   // 112? no: 3584/32 = 112 -- careful: 112
    for (int it = 0; it < KT; ++it) {
        CP_WAIT(1);
        __syncthreads();
        stage_compute<3>(sm0 + (it & 1) * STAGE3, lane, wm, wn, acc);
        __syncthreads();
        if (it + 2 < KT)
            load_fc(sm0 + (it & 1) * STAGE3, fco_w, n0, (it + 2) * 32, tid);
        CP_COMMIT();
    }
#pragma unroll
    for (int mt = 0; mt < 4; ++mt) {
        int r0 = wm * 64 + mt * 16 + (lane >> 2);
#pragma unroll
        for (int nt = 0; nt < 8; ++nt) {
            int n = n0 + wn * 64 + nt * 8 + (lane & 3) * 2;
            float b0 = fco_b[n], b1 = fco_b[n + 1];
            out[(size_t)r0 * VDIM + n] = acc[mt][nt][0] + b0;
            out[(size_t)r0 * VDIM + n + 1] = acc[mt][nt][1] + b1;
            out[(size_t)(r0 + 8) * VDIM + n] = acc[mt][nt][2] + b0;
            out[(size_t)(r0 + 8) * VDIM + n + 1] = acc[mt][nt][3] + b1;
        }
    }
}

// ================= gates: [x|h] @ [w_ih|w_hh]^T, split-K=2, 2-term ===========
__global__ __launch_bounds__(256, 1)
void gates_mma() {
    extern __shared__ char dsm[];
    const uint32_t sm0 = smem_u32(dsm);
    const int tid = threadIdx.x, lane = tid & 31, wid = tid >> 5;
    const int wm = wid >> 2, wn = wid & 3;
    const int n0 = (blockIdx.x & 15) * 256;
    const int ks = blockIdx.x >> 4;
    const int kof = ks * (KCAT / 2);
    float acc[4][8][4] = {};
    gemm_mainloop<2>(g_xh_hi + kof, g_xh_lo + kof, KCAT,
                     g_wg_hi + (size_t)n0 * KCAT + kof, nullptr, KCAT,
                     KCAT / 64, sm0, tid, acc);
    float* gp = g_gatesp[ks];
#pragma unroll
    for (int mt = 0; mt < 4; ++mt) {
        int r0 = wm * 64 + mt * 16 + (lane >> 2);
#pragma unroll
        for (int nt = 0; nt < 8; ++nt) {
            int n = n0 + wn * 64 + nt * 8 + (lane & 3) * 2;
            gp[(size_t)r0 * NG + n] = acc[mt][nt][0];
            gp[(size_t)r0 * NG + n + 1] = acc[mt][nt][1];
            gp[(size_t)(r0 + 8) * NG + n] = acc[mt][nt][2];
            gp[(size_t)(r0 + 8) * NG + n + 1] = acc[mt][nt][3];
        }
    }
}

// ---------------- softmax over seq -------------------------------------------
__global__ void softmax_kernel() {
    __shared__ float sred[SLEN];
    int b = blockIdx.x, s = threadIdx.x;
    float sc = g_score[b * SLEN + s];
    sred[s] = sc; __syncthreads();
    for (int o = SLEN / 2; o > 0; o >>= 1) {
        if (s < o) sred[s] = fmaxf(sred[s], sred[s + o]);
        __syncthreads();
    }
    float m = sred[0]; __syncthreads();
    float e = expf(sc - m);
    sred[s] = e; __syncthreads();
    for (int o = SLEN / 2; o > 0; o >>= 1) {
        if (s < o) sred[s] += sred[s + o];
        __syncthreads();
    }
    g_attn[b * SLEN + s] = e / sred[0];
}

// ---------------- weighted = a @ eo ------------------------------------------
__global__ void weighted_kernel(const float* __restrict__ eo) {
    __shared__ float a_sh[SLEN];
    int b = blockIdx.y;
    int d = blockIdx.x * 256 + threadIdx.x;
    if (threadIdx.x < SLEN) a_sh[threadIdx.x] = g_attn[b * SLEN + threadIdx.x];
    __syncthreads();
    const float* eob = eo + (size_t)b * SLEN * KEO + d;
    float acc = 0.f;
#pragma unroll 8
    for (int s = 0; s < SLEN; ++s) acc = fmaf(a_sh[s], eob[(size_t)s * KEO], acc);
    g_x[(size_t)b * KX + EDIM + d] = acc;
    g_cat[(size_t)b * KCAT + HDIM + d] = acc;
}

// ---------------- LSTM cell elementwise --------------------------------------
__global__ void lstm_kernel(const float* __restrict__ c0,
                            const float* __restrict__ b_ih,
                            const float* __restrict__ b_hh,
                            float* __restrict__ out) {
    int idx = blockIdx.x * blockDim.x + threadIdx.x;   // [0, 128*1024)
    int b = idx >> 10, h = idx & 1023;
    const float* g0 = g_gatesp[0] + (size_t)b * NG;
    const float* g1 = g_gatesp[1] + (size_t)b * NG;
    float ig = g0[h]            + g1[h]            + b_ih[h]            + b_hh[h];
    float fg = g0[HDIM + h]     + g1[HDIM + h]     + b_ih[HDIM + h]     + b_hh[HDIM + h];
    float gg = g0[2 * HDIM + h] + g1[2 * HDIM + h] + b_ih[2 * HDIM + h] + b_hh[2 * HDIM + h];
    float og = g0[3 * HDIM + h] + g1[3 * HDIM + h] + b_ih[3 * HDIM + h] + b_hh[3 * HDIM + h];
    float si = 1.f / (1.f + expf(-ig));
    float sf = 1.f / (1.f + expf(-fg));
    float so = 1.f / (1.f + expf(-og));
    float cn = sf * c0[idx] + si * tanhf(gg);
    float hn = so * tanhf(cn);
    g_cat[(size_t)b * KCAT + h] = hn;
    out[(size_t)BS * VDIM + idx] = hn;                  // h_new
    out[(size_t)BS * VDIM + BS * HDIM + idx] = cn;      // c_new
}

// ---------------- launch -----------------------------------------------------
extern "C" void kernel_launch(void* const* d_in, const int* in_sizes, int n_in,
                              void* d_out, int out_size) {
    const int*   inp_tok = (const int*)  d_in[0];
    const float* h0      = (const float*)d_in[1];
    const float* c0      = (const float*)d_in[2];
    const float* eo      = (const float*)d_in[3];
    const float* emb_w   = (const float*)d_in[4];
    const float* attn_w  = (const float*)d_in[5];
    const float* attn_b  = (const float*)d_in[6];
    const float* v_w     = (const float*)d_in[7];
    const float* w_ih    = (const float*)d_in[8];
    const float* w_hh    = (const float*)d_in[9];
    const float* b_ih    = (const float*)d_in[10];
    const float* b_hh    = (const float*)d_in[11];
    const float* fco_w   = (const float*)d_in[12];
    const float* fco_b   = (const float*)d_in[13];
    float* out = (float*)d_out;

    float* p_hproj;
    cudaGetSymbolAddress((void**)&p_hproj, g_hproj);
    void *p_eo_hi, *p_cat, *p_cat_hi, *p_cat_lo;
    cudaGetSymbolAddress(&p_eo_hi,  g_eo_hi);
    cudaGetSymbolAddress(&p_cat,    g_cat);
    cudaGetSymbolAddress(&p_cat_hi, g_cat_hi);
    cudaGetSymbolAddress(&p_cat_lo, g_cat_lo);

    cudaFuncSetAttribute(attn_mma,  cudaFuncAttributeMaxDynamicSharedMemorySize, DSMEM1);
    cudaFuncSetAttribute(gates_mma, cudaFuncAttributeMaxDynamicSharedMemorySize, DSMEM2);
    cudaFuncSetAttribute(fc_mma,    cudaFuncAttributeMaxDynamicSharedMemorySize, DSMEMF);

    // conversions
    conv_hi<<<(ROWS * (size_t)KEO) / 4 / 256, 256>>>(
        (const float4*)eo, (__half2*)p_eo_hi);
    conv_w_kernel<<<HDIM, 256>>>(attn_w);
    conv_wg_kernel<<<NG, 256>>>(w_ih, w_hh);

    // embedding + h_proj
    embed_kernel<<<BS, 256>>>(inp_tok, emb_w);
    gemm_tn<<<HDIM / TBN, NTHREADS>>>(h0, HDIM, attn_w, 3 * HDIM,
                                      p_hproj, HDIM, HDIM);

    // attention scores (fused GEMM + tanh + v-dot)
    attn_mma<<<256, 256, DSMEM1>>>(attn_b, v_w);
    softmax_kernel<<<BS, SLEN>>>();
    weighted_kernel<<<dim3(KEO / 256, BS), 256>>>(eo);

    // LSTM gates
    conv_xh_kernel<<<BS, 256>>>(h0);
    gates_mma<<<32, 256, DSMEM2>>>();
    lstm_kernel<<<(BS * HDIM) / 256, 256>>>(c0, b_ih, b_hh, out);

    // output projection (in-kernel fco conversion)
    conv_split<<<((size_t)BS * KCAT) / 4 / 256, 256>>>(
        (const float4*)p_cat, (__half2*)p_cat_hi, (__half2*)p_cat_lo);
    fc_mma<<<VDIM / 256, 256, DSMEMF>>>(fco_w, fco_b, out);
}

// round 7
// speedup vs baseline: 4.3280x; 1.2073x over previous
#include <cuda_runtime.h>
#include <cuda_fp16.h>
#include <cstdint>
#include <math.h>

// Problem dims
#define BS   128
#define SLEN 256
#define EDIM 512
#define HDIM 1024
#define VDIM 32000
#define ROWS (BS * SLEN)        // 32768
#define KEO  (2 * HDIM)         // 2048
#define KX   (EDIM + 2 * HDIM)  // 2560
#define KCAT (3 * HDIM + EDIM)  // 3584
#define NG   (4 * HDIM)         // 4096

// SIMT GEMM tile config (h_proj only)
#define TBM 128
#define TBN 64
#define TBK 16
#define NTHREADS 256

// mma.sync tile: CTA 256 thr, tile 128(M) x 256(N), k-step 32
#define PADROW 80               // bytes per 32-half row - conflict-free ldmatrix
#define SM_ALO 10240            // A_lo offset inside stage (NT>=2)
#define SM_BH  20480            // B offset for NT>=2
#define SM_BLO 20480            // B_lo offset relative to B_hi (NT==3)
#define STAGE1 30720
#define STAGE2 40960
#define STAGE3 61440
#define DSMEM1 (3 * STAGE1)     // 92160  (attn, 3-stage)
#define DSMEM2 (3 * STAGE2)     // 122880 (gates & fc, 3-stage)

// ---------------- scratch (device globals; no allocation allowed) ------------
__device__ float g_hproj[BS * HDIM];
__device__ float g_score[ROWS];
__device__ float g_attn[BS * SLEN];
__device__ float g_x[BS * KX];
__device__ float g_cat[BS * KCAT];
__device__ float g_gatesp[2][BS * NG];
__device__ __align__(16) __half g_eo_hi[(size_t)ROWS * KEO];
__device__ __align__(16) __half g_w_hi[(size_t)HDIM * KEO];
__device__ __align__(16) __half g_cat_hi[(size_t)BS * KCAT];
__device__ __align__(16) __half g_cat_lo[(size_t)BS * KCAT];
__device__ __align__(16) __half g_xh_hi[(size_t)BS * KCAT];
__device__ __align__(16) __half g_xh_lo[(size_t)BS * KCAT];
__device__ __align__(16) __half g_wg_hi[(size_t)NG * KCAT];

// ---------------- PTX helpers ------------------------------------------------
__device__ __forceinline__ uint32_t smem_u32(const void* p) {
    uint32_t a;
    asm("{ .reg .u64 t; cvta.to.shared.u64 t, %1; cvt.u32.u64 %0, t; }"
        : "=r"(a) : "l"(p));
    return a;
}

__device__ __forceinline__ void cp16(uint32_t dst, const void* src) {
    asm volatile("cp.async.cg.shared.global [%0], [%1], 16;"
                 :: "r"(dst), "l"(src) : "memory");
}
#define CP_COMMIT() asm volatile("cp.async.commit_group;" ::: "memory")
#define CP_WAIT(n)  asm volatile("cp.async.wait_group %0;" :: "n"(n) : "memory")

__device__ __forceinline__ void ldmx4(uint32_t* r, uint32_t addr) {
    asm volatile("ldmatrix.sync.aligned.m8n8.x4.shared.b16 {%0,%1,%2,%3}, [%4];"
                 : "=r"(r[0]), "=r"(r[1]), "=r"(r[2]), "=r"(r[3]) : "r"(addr));
}

__device__ __forceinline__ void sts128(uint32_t addr, uint32_t a, uint32_t b,
                                       uint32_t c, uint32_t d) {
    asm volatile("st.shared.v4.b32 [%0], {%1,%2,%3,%4};"
                 :: "r"(addr), "r"(a), "r"(b), "r"(c), "r"(d) : "memory");
}

__device__ __forceinline__ uint32_t h2u(__half2 h) {
    return *reinterpret_cast<uint32_t*>(&h);
}

__device__ __forceinline__ void mma16816(float* d, const uint32_t* a,
                                         const uint32_t* b) {
    asm volatile(
        "mma.sync.aligned.m16n8k16.row.col.f32.f16.f16.f32 "
        "{%0,%1,%2,%3}, {%4,%5,%6,%7}, {%8,%9}, {%0,%1,%2,%3};"
        : "+f"(d[0]), "+f"(d[1]), "+f"(d[2]), "+f"(d[3])
        : "r"(a[0]), "r"(a[1]), "r"(a[2]), "r"(a[3]), "r"(b[0]), "r"(b[1]));
}

__device__ __forceinline__ float ftanh(float x) {
    float e = __expf(2.f * x);
    return 1.f - 2.f / (e + 1.f);
}

// ---------------- split-fp16 mma machinery -----------------------------------
// NT=1: A hi, B hi. NT=2: A hi+lo, B hi.
template<int NT>
__device__ __forceinline__ void stage_load(
    uint32_t sbase,
    const __half* __restrict__ Ah, const __half* __restrict__ Al, int lda,
    const __half* __restrict__ Bh, int ldb, int tid, int kof)
{
    constexpr uint32_t BOFF = (NT == 1) ? 10240 : SM_BH;
#pragma unroll
    for (int i = 0; i < 2; ++i) {           // A: 128 rows x 32 k
        int idx = tid + 256 * i;
        int r = idx >> 2, c = idx & 3;
        uint32_t d = sbase + r * PADROW + c * 16;
        size_t go = (size_t)r * lda + kof + c * 8;
        cp16(d, Ah + go);
        if (NT >= 2) cp16(d + SM_ALO, Al + go);
    }
#pragma unroll
    for (int i = 0; i < 4; ++i) {           // B: 256 rows x 32 k
        int idx = tid + 256 * i;
        int r = idx >> 2, c = idx & 3;
        uint32_t d = sbase + BOFF + r * PADROW + c * 16;
        size_t go = (size_t)r * ldb + kof + c * 8;
        cp16(d, Bh + go);
    }
}

template<int NT>
__device__ __forceinline__ void stage_compute(uint32_t sbase, int lane,
                                              int wm, int wn,
                                              float (&acc)[4][8][4])
{
    constexpr uint32_t BOFF = (NT == 1) ? 10240 : SM_BH;
    const uint32_t a_row = wm * 64 + (lane & 7) + ((lane >> 3) & 1) * 8;
    const uint32_t a_colb = (lane >> 4) * 16;
    const uint32_t b_row = wn * 64 + (lane & 7) + ((lane >> 4) & 1) * 8;
    const uint32_t b_colb = ((lane >> 3) & 1) * 16;
#pragma unroll
    for (int kk = 0; kk < 2; ++kk) {
        uint32_t ahi[4][4], alo[4][4], bfr[4][4];
        const uint32_t ka = sbase + a_row * PADROW + a_colb + kk * 32;
#pragma unroll
        for (int mt = 0; mt < 4; ++mt) {
            ldmx4(ahi[mt], ka + mt * 16 * PADROW);
            if (NT >= 2) ldmx4(alo[mt], ka + mt * 16 * PADROW + SM_ALO);
        }
        const uint32_t kb = sbase + BOFF + b_row * PADROW + b_colb + kk * 32;
#pragma unroll
        for (int np = 0; np < 4; ++np) ldmx4(bfr[np], kb + np * 16 * PADROW);
#pragma unroll
        for (int mt = 0; mt < 4; ++mt)
#pragma unroll
            for (int np = 0; np < 4; ++np) {
                mma16816(acc[mt][np * 2],     ahi[mt], &bfr[np][0]);
                mma16816(acc[mt][np * 2 + 1], ahi[mt], &bfr[np][2]);
                if (NT >= 2) {
                    mma16816(acc[mt][np * 2],     alo[mt], &bfr[np][0]);
                    mma16816(acc[mt][np * 2 + 1], alo[mt], &bfr[np][2]);
                }
            }
    }
}

template<int NT>
__device__ __forceinline__ void gemm_mainloop(
    const __half* Ah, const __half* Al, int lda,
    const __half* Bh, int ldb,
    int KT, uint32_t sm0, int tid, float (&acc)[4][8][4])
{
    constexpr uint32_t STG = (NT == 1) ? STAGE1 : STAGE2;
    const int lane = tid & 31, wid = tid >> 5;
    const int wm = wid >> 2, wn = wid & 3;
    stage_load<NT>(sm0, Ah, Al, lda, Bh, ldb, tid, 0);
    CP_COMMIT();
    stage_load<NT>(sm0 + STG, Ah, Al, lda, Bh, ldb, tid, 32);
    CP_COMMIT();
    int sl = 2, sc = 0;
    for (int it = 0; it < KT; ++it) {
        CP_WAIT(1);
        __syncthreads();
        if (it + 2 < KT)
            stage_load<NT>(sm0 + sl * STG, Ah, Al, lda, Bh, ldb,
                           tid, (it + 2) * 32);
        CP_COMMIT();
        stage_compute<NT>(sm0 + sc * STG, lane, wm, wn, acc);
        if (++sl == 3) sl = 0;
        if (++sc == 3) sc = 0;
    }
}

// ---------------- conversions -------------------------------------------------
__global__ void conv_hi(const float4* __restrict__ src,
                        __half2* __restrict__ hi) {
    size_t i = (size_t)blockIdx.x * blockDim.x + threadIdx.x;
    float4 v = src[i];
    hi[i * 2 + 0] = __floats2half2_rn(v.x, v.y);
    hi[i * 2 + 1] = __floats2half2_rn(v.z, v.w);
}

__global__ void conv_split(const float4* __restrict__ src,
                           __half2* __restrict__ hi,
                           __half2* __restrict__ lo) {
    size_t i = (size_t)blockIdx.x * blockDim.x + threadIdx.x;
    float4 v = src[i];
    __half2 h0 = __floats2half2_rn(v.x, v.y);
    __half2 h1 = __floats2half2_rn(v.z, v.w);
    float2 f0 = __half22float2(h0);
    float2 f1 = __half22float2(h1);
    hi[i * 2 + 0] = h0;
    hi[i * 2 + 1] = h1;
    lo[i * 2 + 0] = __floats2half2_rn(v.x - f0.x, v.y - f0.y);
    lo[i * 2 + 1] = __floats2half2_rn(v.z - f1.x, v.w - f1.y);
}

// gather attn_w[:, H:3H] -> g_w_hi [HDIM x KEO]
__global__ void conv_w_kernel(const float* __restrict__ attn_w) {
    int n = blockIdx.x;
    const float2* src = (const float2*)(attn_w + (size_t)n * 3 * HDIM + HDIM);
    __half2* hi = (__half2*)(g_w_hi + (size_t)n * KEO);
    for (int c = threadIdx.x; c < KEO / 2; c += blockDim.x) {
        float2 v = src[c];
        hi[c] = __floats2half2_rn(v.x, v.y);
    }
}

// [w_ih | w_hh] rows -> g_wg_hi [NG x KCAT]
__global__ void conv_wg_kernel(const float* __restrict__ w_ih,
                               const float* __restrict__ w_hh) {
    int n = blockIdx.x;
    for (int k = threadIdx.x; k < KCAT; k += blockDim.x) {
        float v = (k < KX) ? w_ih[(size_t)n * KX + k]
                           : w_hh[(size_t)n * HDIM + (k - KX)];
        g_wg_hi[(size_t)n * KCAT + k] = __float2half_rn(v);
    }
}

// [x | h0] rows -> g_xh hi/lo [BS x KCAT]
__global__ void conv_xh_kernel(const float* __restrict__ h0) {
    int b = blockIdx.x;
    for (int k = threadIdx.x; k < KCAT; k += blockDim.x) {
        float v = (k < KX) ? g_x[(size_t)b * KX + k]
                           : h0[(size_t)b * HDIM + (k - KX)];
        __half h = __float2half_rn(v);
        g_xh_hi[(size_t)b * KCAT + k] = h;
        g_xh_lo[(size_t)b * KCAT + k] = __float2half_rn(v - __half2float(h));
    }
}

// ---------------- embedding gather ------------------------------------------
__global__ void embed_kernel(const int* __restrict__ tok,
                             const float* __restrict__ emb_w) {
    int b = blockIdx.x;
    int t = tok[b];
    for (int e = threadIdx.x; e < EDIM; e += blockDim.x) {
        float v = emb_w[(size_t)t * EDIM + e];
        g_x[(size_t)b * KX + e] = v;
        g_cat[(size_t)b * KCAT + 3 * HDIM + e] = v;
    }
}

// ---------------- SIMT GEMM (h_proj only) ------------------------------------
__global__ __launch_bounds__(NTHREADS)
void gemm_tn(const float* __restrict__ A, int lda,
             const float* __restrict__ B, int ldb,
             float* __restrict__ C, int ldc, int K) {
    __shared__ float As[TBK][TBM];
    __shared__ float Bs[TBK][TBN];
    const int tid = threadIdx.x;
    const int col0 = blockIdx.x * TBN;
    const int tm0 = (tid >> 4) * 8;
    const int tn0 = (tid & 15) * 4;
    float acc[8][4] = {};
    for (int k0 = 0; k0 < K; k0 += TBK) {
#pragma unroll
        for (int t = 0; t < 2; ++t) {
            int lin = (tid + t * NTHREADS) * 4;
            int r = lin >> 4, cc = lin & 15;
            float4 v = *(const float4*)(A + (size_t)r * lda + k0 + cc);
            As[cc + 0][r] = v.x; As[cc + 1][r] = v.y;
            As[cc + 2][r] = v.z; As[cc + 3][r] = v.w;
        }
        {
            int lin = tid * 4;
            int r = lin >> 4, cc = lin & 15;
            float4 v = *(const float4*)(B + (size_t)(col0 + r) * ldb + k0 + cc);
            Bs[cc + 0][r] = v.x; Bs[cc + 1][r] = v.y;
            Bs[cc + 2][r] = v.z; Bs[cc + 3][r] = v.w;
        }
        __syncthreads();
#pragma unroll
        for (int k = 0; k < TBK; ++k) {
            float4 a0 = *(const float4*)&As[k][tm0];
            float4 a1 = *(const float4*)&As[k][tm0 + 4];
            float4 b0 = *(const float4*)&Bs[k][tn0];
            float a[8] = {a0.x, a0.y, a0.z, a0.w, a1.x, a1.y, a1.z, a1.w};
            float b[4] = {b0.x, b0.y, b0.z, b0.w};
#pragma unroll
            for (int i = 0; i < 8; ++i)
#pragma unroll
                for (int j = 0; j < 4; ++j)
                    acc[i][j] = fmaf(a[i], b[j], acc[i][j]);
        }
        __syncthreads();
    }
#pragma unroll
    for (int i = 0; i < 8; ++i)
#pragma unroll
        for (int j = 0; j < 4; ++j)
            C[(size_t)(tm0 + i) * ldc + col0 + tn0 + j] = acc[i][j];
}

// ================= attention energy: 1-term fp16 mma + fused epilogue ========
__global__ __launch_bounds__(256, 1)
void attn_mma(const float* __restrict__ attn_b, const float* __restrict__ v_w) {
    extern __shared__ char dsm[];
    __shared__ float base_sh[256], v_sh[256], red[4][128];
    const uint32_t sm0 = smem_u32(dsm);
    const int tid = threadIdx.x, lane = tid & 31, wid = tid >> 5;
    const int wm = wid >> 2, wn = wid & 3;
    const int row0 = blockIdx.x * 128;
    const int b_idx = row0 >> 8;

    float rowpart[4][2] = {};
    for (int ch = 0; ch < 4; ++ch) {
        const int n0 = ch * 256;
        __syncthreads();
        base_sh[tid] = g_hproj[(size_t)b_idx * HDIM + n0 + tid] + attn_b[n0 + tid];
        v_sh[tid] = v_w[n0 + tid];
        float acc[4][8][4] = {};
        gemm_mainloop<1>(g_eo_hi + (size_t)row0 * KEO, nullptr, KEO,
                         g_w_hi + (size_t)n0 * KEO, KEO,
                         64, sm0, tid, acc);
#pragma unroll
        for (int mt = 0; mt < 4; ++mt)
#pragma unroll
            for (int nt = 0; nt < 8; ++nt) {
                int nb = wn * 64 + nt * 8 + (lane & 3) * 2;
                float b0 = base_sh[nb], b1 = base_sh[nb + 1];
                float v0 = v_sh[nb], v1 = v_sh[nb + 1];
                rowpart[mt][0] += v0 * ftanh(acc[mt][nt][0] + b0)
                                + v1 * ftanh(acc[mt][nt][1] + b1);
                rowpart[mt][1] += v0 * ftanh(acc[mt][nt][2] + b0)
                                + v1 * ftanh(acc[mt][nt][3] + b1);
            }
    }
#pragma unroll
    for (int mt = 0; mt < 4; ++mt)
#pragma unroll
        for (int h = 0; h < 2; ++h) {
            float v = rowpart[mt][h];
            v += __shfl_xor_sync(0xffffffff, v, 1);
            v += __shfl_xor_sync(0xffffffff, v, 2);
            if ((lane & 3) == 0)
                red[wn][wm * 64 + mt * 16 + (lane >> 2) + 8 * h] = v;
        }
    __syncthreads();
    if (tid < 128)
        g_score[row0 + tid] = red[0][tid] + red[1][tid] + red[2][tid] + red[3][tid];
}

// ================= fc: 2-term, B (fco_w) fp32->fp16 in-kernel, 3-stage =======
// Register-prefetched B: LDG for iter it+3 issued before compute of iter it.
__device__ __forceinline__ void ldg_fcB(const float* __restrict__ fco,
                                        int n0, int kof, int tid, float4* r) {
    const float4* src = (const float4*)(fco + (size_t)(n0 + tid) * KCAT + kof);
#pragma unroll
    for (int j = 0; j < 8; ++j) r[j] = src[j];
}

__device__ __forceinline__ void sts_fcB(uint32_t sbase, int tid,
                                        const float4* r) {
    uint32_t bh = sbase + SM_BH + tid * PADROW;
#pragma unroll
    for (int j = 0; j < 8; j += 2) {
        __half2 h0 = __floats2half2_rn(r[j].x,     r[j].y);
        __half2 h1 = __floats2half2_rn(r[j].z,     r[j].w);
        __half2 h2 = __floats2half2_rn(r[j + 1].x, r[j + 1].y);
        __half2 h3 = __floats2half2_rn(r[j + 1].z, r[j + 1].w);
        sts128(bh + j * 8, h2u(h0), h2u(h1), h2u(h2), h2u(h3));
    }
}

__device__ __forceinline__ void cp_fcA(uint32_t sbase, int kof, int tid) {
#pragma unroll
    for (int i = 0; i < 2; ++i) {
        int idx = tid + 256 * i;
        int r = idx >> 2, c = idx & 3;
        uint32_t d = sbase + r * PADROW + c * 16;
        size_t go = (size_t)r * KCAT + kof + c * 8;
        cp16(d, g_cat_hi + go);
        cp16(d + SM_ALO, g_cat_lo + go);
    }
}

__global__ __launch_bounds__(256, 1)
void fc_mma(const float* __restrict__ fco_w, const float* __restrict__ fco_b,
            float* __restrict__ out) {
    extern __shared__ char dsm[];
    const uint32_t sm0 = smem_u32(dsm);
    const int tid = threadIdx.x, lane = tid & 31, wid = tid >> 5;
    const int wm = wid >> 2, wn = wid & 3;
    const int n0 = blockIdx.x * 256;
    const int KT = KCAT / 32;   // 112
    float acc[4][8][4] = {};
    float4 br[8];

    ldg_fcB(fco_w, n0, 0, tid, br);
    sts_fcB(sm0, tid, br);
    cp_fcA(sm0, 0, tid);
    CP_COMMIT();
    ldg_fcB(fco_w, n0, 32, tid, br);
    sts_fcB(sm0 + STAGE2, tid, br);
    cp_fcA(sm0 + STAGE2, 32, tid);
    CP_COMMIT();
    ldg_fcB(fco_w, n0, 64, tid, br);

    for (int it = 0; it < KT; ++it) {
        CP_WAIT(1);
        __syncthreads();
        const int s2 = (it + 2) % 3;
        if (it + 2 < KT) {
            sts_fcB(sm0 + s2 * STAGE2, tid, br);
            cp_fcA(sm0 + s2 * STAGE2, (it + 2) * 32, tid);
        }
        CP_COMMIT();
        if (it + 3 < KT) ldg_fcB(fco_w, n0, (it + 3) * 32, tid, br);
        stage_compute<2>(sm0 + (it % 3) * STAGE2, lane, wm, wn, acc);
    }
#pragma unroll
    for (int mt = 0; mt < 4; ++mt) {
        int r0 = wm * 64 + mt * 16 + (lane >> 2);
#pragma unroll
        for (int nt = 0; nt < 8; ++nt) {
            int n = n0 + wn * 64 + nt * 8 + (lane & 3) * 2;
            float b0 = fco_b[n], b1 = fco_b[n + 1];
            out[(size_t)r0 * VDIM + n] = acc[mt][nt][0] + b0;
            out[(size_t)r0 * VDIM + n + 1] = acc[mt][nt][1] + b1;
            out[(size_t)(r0 + 8) * VDIM + n] = acc[mt][nt][2] + b0;
            out[(size_t)(r0 + 8) * VDIM + n + 1] = acc[mt][nt][3] + b1;
        }
    }
}

// ================= gates: [x|h] @ [w_ih|w_hh]^T, split-K=2, 2-term ===========
__global__ __launch_bounds__(256, 1)
void gates_mma() {
    extern __shared__ char dsm[];
    const uint32_t sm0 = smem_u32(dsm);
    const int tid = threadIdx.x, lane = tid & 31, wid = tid >> 5;
    const int wm = wid >> 2, wn = wid & 3;
    const int n0 = (blockIdx.x & 15) * 256;
    const int ks = blockIdx.x >> 4;
    const int kof = ks * (KCAT / 2);
    float acc[4][8][4] = {};
    gemm_mainloop<2>(g_xh_hi + kof, g_xh_lo + kof, KCAT,
                     g_wg_hi + (size_t)n0 * KCAT + kof, KCAT,
                     KCAT / 64, sm0, tid, acc);
    float* gp = g_gatesp[ks];
#pragma unroll
    for (int mt = 0; mt < 4; ++mt) {
        int r0 = wm * 64 + mt * 16 + (lane >> 2);
#pragma unroll
        for (int nt = 0; nt < 8; ++nt) {
            int n = n0 + wn * 64 + nt * 8 + (lane & 3) * 2;
            gp[(size_t)r0 * NG + n] = acc[mt][nt][0];
            gp[(size_t)r0 * NG + n + 1] = acc[mt][nt][1];
            gp[(size_t)(r0 + 8) * NG + n] = acc[mt][nt][2];
            gp[(size_t)(r0 + 8) * NG + n + 1] = acc[mt][nt][3];
        }
    }
}

// ---------------- softmax over seq -------------------------------------------
__global__ void softmax_kernel() {
    __shared__ float sred[SLEN];
    int b = blockIdx.x, s = threadIdx.x;
    float sc = g_score[b * SLEN + s];
    sred[s] = sc; __syncthreads();
    for (int o = SLEN / 2; o > 0; o >>= 1) {
        if (s < o) sred[s] = fmaxf(sred[s], sred[s + o]);
        __syncthreads();
    }
    float m = sred[0]; __syncthreads();
    float e = expf(sc - m);
    sred[s] = e; __syncthreads();
    for (int o = SLEN / 2; o > 0; o >>= 1) {
        if (s < o) sred[s] += sred[s + o];
        __syncthreads();
    }
    g_attn[b * SLEN + s] = e / sred[0];
}

// ---------------- weighted = a @ eo (reads fp16 eo_hi) -----------------------
__global__ void weighted_kernel() {
    __shared__ float a_sh[SLEN];
    int b = blockIdx.y;
    int d = blockIdx.x * 256 + threadIdx.x;
    if (threadIdx.x < SLEN) a_sh[threadIdx.x] = g_attn[b * SLEN + threadIdx.x];
    __syncthreads();
    const __half* eob = g_eo_hi + (size_t)b * SLEN * KEO + d;
    float acc = 0.f;
#pragma unroll 8
    for (int s = 0; s < SLEN; ++s)
        acc = fmaf(a_sh[s], __half2float(eob[(size_t)s * KEO]), acc);
    g_x[(size_t)b * KX + EDIM + d] = acc;
    g_cat[(size_t)b * KCAT + HDIM + d] = acc;
}

// ---------------- LSTM cell elementwise --------------------------------------
__global__ void lstm_kernel(const float* __restrict__ c0,
                            const float* __restrict__ b_ih,
                            const float* __restrict__ b_hh,
                            float* __restrict__ out) {
    int idx = blockIdx.x * blockDim.x + threadIdx.x;   // [0, 128*1024)
    int b = idx >> 10, h = idx & 1023;
    const float* g0 = g_gatesp[0] + (size_t)b * NG;
    const float* g1 = g_gatesp[1] + (size_t)b * NG;
    float ig = g0[h]            + g1[h]            + b_ih[h]            + b_hh[h];
    float fg = g0[HDIM + h]     + g1[HDIM + h]     + b_ih[HDIM + h]     + b_hh[HDIM + h];
    float gg = g0[2 * HDIM + h] + g1[2 * HDIM + h] + b_ih[2 * HDIM + h] + b_hh[2 * HDIM + h];
    float og = g0[3 * HDIM + h] + g1[3 * HDIM + h] + b_ih[3 * HDIM + h] + b_hh[3 * HDIM + h];
    float si = 1.f / (1.f + expf(-ig));
    float sf = 1.f / (1.f + expf(-fg));
    float so = 1.f / (1.f + expf(-og));
    float cn = sf * c0[idx] + si * tanhf(gg);
    float hn = so * tanhf(cn);
    g_cat[(size_t)b * KCAT + h] = hn;
    out[(size_t)BS * VDIM + idx] = hn;                  // h_new
    out[(size_t)BS * VDIM + BS * HDIM + idx] = cn;      // c_new
}

// ---------------- launch -----------------------------------------------------
extern "C" void kernel_launch(void* const* d_in, const int* in_sizes, int n_in,
                              void* d_out, int out_size) {
    const int*   inp_tok = (const int*)  d_in[0];
    const float* h0      = (const float*)d_in[1];
    const float* c0      = (const float*)d_in[2];
    const float* eo      = (const float*)d_in[3];
    const float* emb_w   = (const float*)d_in[4];
    const float* attn_w  = (const float*)d_in[5];
    const float* attn_b  = (const float*)d_in[6];
    const float* v_w     = (const float*)d_in[7];
    const float* w_ih    = (const float*)d_in[8];
    const float* w_hh    = (const float*)d_in[9];
    const float* b_ih    = (const float*)d_in[10];
    const float* b_hh    = (const float*)d_in[11];
    const float* fco_w   = (const float*)d_in[12];
    const float* fco_b   = (const float*)d_in[13];
    float* out = (float*)d_out;

    float* p_hproj;
    cudaGetSymbolAddress((void**)&p_hproj, g_hproj);
    void *p_eo_hi, *p_cat, *p_cat_hi, *p_cat_lo;
    cudaGetSymbolAddress(&p_eo_hi,  g_eo_hi);
    cudaGetSymbolAddress(&p_cat,    g_cat);
    cudaGetSymbolAddress(&p_cat_hi, g_cat_hi);
    cudaGetSymbolAddress(&p_cat_lo, g_cat_lo);

    cudaFuncSetAttribute(attn_mma,  cudaFuncAttributeMaxDynamicSharedMemorySize, DSMEM1);
    cudaFuncSetAttribute(gates_mma, cudaFuncAttributeMaxDynamicSharedMemorySize, DSMEM2);
    cudaFuncSetAttribute(fc_mma,    cudaFuncAttributeMaxDynamicSharedMemorySize, DSMEM2);

    // conversions
    conv_hi<<<(ROWS * (size_t)KEO) / 4 / 256, 256>>>(
        (const float4*)eo, (__half2*)p_eo_hi);
    conv_w_kernel<<<HDIM, 256>>>(attn_w);
    conv_wg_kernel<<<NG, 256>>>(w_ih, w_hh);

    // embedding + h_proj
    embed_kernel<<<BS, 256>>>(inp_tok, emb_w);
    gemm_tn<<<HDIM / TBN, NTHREADS>>>(h0, HDIM, attn_w, 3 * HDIM,
                                      p_hproj, HDIM, HDIM);

    // attention scores (fused GEMM + tanh + v-dot)
    attn_mma<<<256, 256, DSMEM1>>>(attn_b, v_w);
    softmax_kernel<<<BS, SLEN>>>();
    weighted_kernel<<<dim3(KEO / 256, BS), 256>>>();

    // LSTM gates
    conv_xh_kernel<<<BS, 256>>>(h0);
    gates_mma<<<32, 256, DSMEM2>>>();
    lstm_kernel<<<(BS * HDIM) / 256, 256>>>(c0, b_ih, b_hh, out);

    // output projection (in-kernel fco conversion, 2-term, 3-stage)
    conv_split<<<((size_t)BS * KCAT) / 4 / 256, 256>>>(
        (const float4*)p_cat, (__half2*)p_cat_hi, (__half2*)p_cat_lo);
    fc_mma<<<VDIM / 256, 256, DSMEM2>>>(fco_w, fco_b, out);
}